// round 13
// baseline (speedup 1.0000x reference)
#include <cuda_runtime.h>
#include <math.h>
#include <stdint.h>

#define Bb   64
#define Tt   2048
#define LDIM 16
#define HDIM 64
#define Kk   8
#define LC   16
#define CC   128             // Tt / LC
#define SCn  16              // chunks per superchunk
#define NS   8               // superchunks per batch = CC/SCn

#define LOG2E  1.4426950408889634f
#define LN2F   0.6931471805599453f
#define LOG2PI 1.8378770664093453f

#define GSZ  (Bb*Tt*Kk)            // gamma elements
#define PSZ  (Bb*(Tt-1)*Kk*Kk)     // paired elements

typedef unsigned long long u64;

// ---------------- f32x2 / MUFU helpers ----------------
__device__ __forceinline__ u64 fma2(u64 a, u64 b, u64 c){
    u64 d; asm("fma.rn.f32x2 %0, %1, %2, %3;" : "=l"(d) : "l"(a), "l"(b), "l"(c)); return d;
}
__device__ __forceinline__ u64 mul2(u64 a, u64 b){
    u64 d; asm("mul.rn.f32x2 %0, %1, %2;" : "=l"(d) : "l"(a), "l"(b)); return d;
}
__device__ __forceinline__ u64 packbb(float x){
    u64 d; asm("mov.b64 %0, {%1, %1};" : "=l"(d) : "f"(x)); return d;
}
__device__ __forceinline__ u64 pack2(float x, float y){
    u64 d; asm("mov.b64 %0, {%1, %2};" : "=l"(d) : "f"(x), "f"(y)); return d;
}
__device__ __forceinline__ float2 unpk(u64 u){
    float2 f; asm("mov.b64 {%0, %1}, %2;" : "=f"(f.x), "=f"(f.y) : "l"(u)); return f;
}
__device__ __forceinline__ float ex2(float x){ float r; asm("ex2.approx.ftz.f32 %0, %1;" : "=f"(r) : "f"(x)); return r; }
__device__ __forceinline__ float lg2(float x){ float r; asm("lg2.approx.f32 %0, %1;" : "=f"(r) : "f"(x)); return r; }

// ---------------- scratch ----------------
__device__ __align__(16) float g_ele[Bb*Tt*Kk];   // exp(le - m_t)
__device__ float g_m  [Bb*Tt];                    // m_t = max_k le
__device__ __align__(16) float g_A  [Bb*Tt*Kk];   // scaled forward
__device__ __align__(16) float g_Bv [Bb*Tt*Kk];   // scaled backward
__device__ float g_sig[Bb*Tt];                    // sum_k a-hat_t
__device__ int   g_E  [Bb*Tt];
__device__ int   g_F  [Bb*Tt];
__device__ __align__(16) float g_M  [Bb*CC*64];   // chunk matrices
__device__ int   g_EM [Bb*CC];
__device__ __align__(16) float g_SM [Bb*NS*64];   // superchunk matrices
__device__ int   g_ESM[Bb*NS];
__device__ __align__(16) float g_eQ [64];
__device__ float g_epi[8];
__device__ float g_Qlog[64];
__device__ float g_logpi[8];
__device__ float g_Linv0[Kk*LDIM*LDIM];
__device__ float g_LinvT[Kk*LDIM*LDIM];
__device__ float g_ld0[Kk];
__device__ float g_ldT[Kk];

__device__ __forceinline__ int rescale8(float* v) {
    float mx = v[0];
    #pragma unroll
    for (int k = 1; k < 8; k++) mx = fmaxf(mx, v[k]);
    int ib = __float_as_int(mx);
    int ee = (ib >> 23) - 127;
    float sc = __int_as_float((254 - (ib >> 23)) << 23);
    #pragma unroll
    for (int k = 0; k < 8; k++) v[k] *= sc;
    return ee;
}

__device__ __forceinline__ void load8(float* dst, const float* src) {
    float4 a = *(const float4*)src;
    float4 b = *(const float4*)(src + 4);
    dst[0]=a.x; dst[1]=a.y; dst[2]=a.z; dst[3]=a.w;
    dst[4]=b.x; dst[5]=b.y; dst[6]=b.z; dst[7]=b.w;
}
__device__ __forceinline__ void store8(float* dst, const float* v) {
    *(float4*)dst       = make_float4(v[0], v[1], v[2], v[3]);
    *(float4*)(dst + 4) = make_float4(v[4], v[5], v[6], v[7]);
}

// ---------------- prep ----------------
__global__ void snlds_prep(const float* __restrict__ pi,
                           const float* __restrict__ Q,
                           const float* __restrict__ init_cov,
                           const float* __restrict__ covs)
{
    __shared__ float S[16][256];
    int tid = threadIdx.x;         // 256 threads

    for (int e = tid; e < 4096; e += 256) {
        int m  = e >> 8;
        int ij = e & 255;
        int i  = ij >> 4, j = ij & 15;
        const float* C = (m < 8) ? (init_cov + m*256) : (covs + (m-8)*256);
        float s = (i == j) ? 1e-6f : 0.0f;
        #pragma unroll
        for (int d = 0; d < 16; d++) s = fmaf(C[i*16+d], C[j*16+d], s);
        S[m][ij] = s;
    }
    __syncthreads();

    int m = tid >> 4, r = tid & 15;
    for (int kk = 0; kk < 16; kk++) {
        if (r == kk) {
            float s = S[m][kk*16+kk];
            for (int e2 = 0; e2 < kk; e2++) { float v = S[m][kk*16+e2]; s -= v*v; }
            S[m][kk*16+kk] = sqrtf(s);
        }
        __syncthreads();
        if (r > kk) {
            float s = S[m][r*16+kk];
            for (int e2 = 0; e2 < kk; e2++) s -= S[m][r*16+e2]*S[m][kk*16+e2];
            S[m][r*16+kk] = s / S[m][kk*16+kk];
        }
        __syncthreads();
    }

    if (r == 0) {
        float s = 0.f;
        for (int d = 0; d < 16; d++) s += logf(S[m][d*16+d]);
        if (m < 8) g_ld0[m] = s; else g_ldT[m-8] = s;
    }

    {
        int c = r;
        float x[16];
        #pragma unroll
        for (int i2 = 0; i2 < 16; i2++) x[i2] = 0.f;
        for (int i2 = c; i2 < 16; i2++) {
            float s = (i2 == c) ? 1.0f : 0.0f;
            for (int e2 = c; e2 < i2; e2++) s -= S[m][i2*16+e2]*x[e2];
            x[i2] = s / S[m][i2*16+i2];
        }
        float* dst = (m < 8) ? (g_Linv0 + m*256) : (g_LinvT + (m-8)*256);
        for (int i2 = 0; i2 < 16; i2++) dst[i2*16 + c] = x[i2];
    }

    if (tid < 8) {
        float mx = -1e30f;
        for (int j = 0; j < 8; j++) mx = fmaxf(mx, Q[tid*8+j]);
        float se = 0.f;
        for (int j = 0; j < 8; j++) se += expf(Q[tid*8+j]-mx);
        float l = mx + logf(se);
        for (int j = 0; j < 8; j++) g_Qlog[tid*8+j] = Q[tid*8+j] - l;
    }
    if (tid == 8) {
        float mx = -1e30f;
        for (int j = 0; j < 8; j++) mx = fmaxf(mx, pi[j]);
        float se = 0.f;
        for (int j = 0; j < 8; j++) se += expf(pi[j]-mx);
        float l = mx + logf(se);
        for (int j = 0; j < 8; j++) g_logpi[j] = pi[j] - l;
    }
    __syncthreads();
    if (tid < 64) g_eQ[tid] = expf(g_Qlog[tid]);
    if (tid < 8)  g_epi[tid] = expf(g_logpi[tid]);
}

// ---------------- emissions: t>=1, 2 t per thread, 74.5KB smem ----------------
#define OFF_W1   0            // [k][d][j] * LOG2E  8192
#define OFF_W2   8192         // [k][j][d] * LN2F   8192
#define OFF_LVT  16384        // [k][e][d]          2048
#define OFF_B1   18432        // [k][j] * LOG2E     512
#define OFF_B2   18944        // [k][d]             128
#define OFF_LDT  19072        // 8
#define EMIS_SMEM_FLOATS 19080
#define EMIS_SMEM_BYTES  (EMIS_SMEM_FLOATS*4)

__device__ __forceinline__ float maha16(const u64* dd, const float* LT) {
    u64 dbb[16];
    #pragma unroll
    for (int x = 0; x < 8; x++) {
        float2 f = unpk(dd[x]);
        dbb[2*x]   = packbb(f.x);
        dbb[2*x+1] = packbb(f.y);
    }
    u64 y2[8];
    #pragma unroll
    for (int x = 0; x < 8; x++) y2[x] = 0ull;
    #pragma unroll
    for (int e = 0; e < 16; e++) {
        #pragma unroll
        for (int x = 0; x < 8; x++)
            y2[x] = fma2(*(const u64*)(LT + e*16 + 2*x), dbb[e], y2[x]);
    }
    u64 m2 = 0ull;
    #pragma unroll
    for (int x = 0; x < 8; x++) m2 = fma2(y2[x], y2[x], m2);
    float2 mm = unpk(m2);
    return mm.x + mm.y;
}

__global__ void __launch_bounds__(128) snlds_emis(const float* __restrict__ z,
                                                  const float* __restrict__ W1,
                                                  const float* __restrict__ b1,
                                                  const float* __restrict__ W2,
                                                  const float* __restrict__ b2)
{
    extern __shared__ float sm[];
    int tx = threadIdx.x;

    for (int i = tx; i < 8192; i += 128) {
        int k = i >> 10, rem = i & 1023;
        int j = rem >> 4, d = rem & 15;
        sm[OFF_W1 + k*1024 + d*64 + j] = LOG2E * W1[i];
        int d2 = rem >> 6, j2 = rem & 63;
        sm[OFF_W2 + k*1024 + j2*16 + d2] = LN2F * W2[i];
    }
    for (int i = tx; i < 2048; i += 128) {
        int k = i >> 8, rem = i & 255;
        int d = rem >> 4, e = rem & 15;
        sm[OFF_LVT + k*256 + e*16 + d] = g_LinvT[i];
    }
    for (int i = tx; i < 512; i += 128) sm[OFF_B1 + i] = LOG2E * b1[i];
    if (tx < 128) sm[OFF_B2 + tx] = b2[tx];
    if (tx < 8) sm[OFF_LDT + tx] = g_ldT[tx];
    __syncthreads();

    int p = blockIdx.x*128 + tx;         // 65536 t-pairs
    int b = p >> 10;
    int t0 = (p & 1023) << 1;
    const float* zb = z + ((size_t)b*Tt + t0)*LDIM;

    u64 v0bb[16], v1bb[16];
    {
        float tmp[16];
        const float* z0 = (p == 0) ? zb : (zb - LDIM);   // OOB clamp only
        load8(tmp, z0); load8(tmp+8, z0+8);
        #pragma unroll
        for (int d = 0; d < 16; d++) v0bb[d] = packbb(tmp[d]);
        load8(tmp, zb); load8(tmp+8, zb+8);
        #pragma unroll
        for (int d = 0; d < 16; d++) v1bb[d] = packbb(tmp[d]);
    }

    float le0[8], le1[8];

    #pragma unroll 1
    for (int k = 0; k < 8; k++) {
        const float* w1k = sm + OFF_W1 + k*1024;
        const float* w2k = sm + OFF_W2 + k*1024;
        u64 mu0[8], mu1[8];
        #pragma unroll
        for (int x = 0; x < 8; x++) {
            u64 bp = *(const u64*)(sm + OFF_B2 + k*16 + 2*x);
            mu0[x] = bp; mu1[x] = bp;
        }
        #pragma unroll 1
        for (int jg = 0; jg < 16; jg++) {
            const float* w1j = w1k + jg*4;
            u64 bA = *(const u64*)(sm + OFF_B1 + k*64 + jg*4);
            u64 bB = *(const u64*)(sm + OFF_B1 + k*64 + jg*4 + 2);
            u64 aA0 = bA, aA1 = bA, aB0 = bB, aB1 = bB;
            #pragma unroll
            for (int d = 0; d < 16; d++) {
                u64 wA = *(const u64*)(w1j + d*64);
                u64 wB = *(const u64*)(w1j + d*64 + 2);
                aA0 = fma2(wA, v0bb[d], aA0);
                aA1 = fma2(wA, v1bb[d], aA1);
                aB0 = fma2(wB, v0bb[d], aB0);
                aB1 = fma2(wB, v1bb[d], aB1);
            }
            float2 fA0 = unpk(aA0), fB0 = unpk(aB0), fA1 = unpk(aA1), fB1 = unpk(aB1);
            u64 h00 = packbb(lg2(1.0f + ex2(fA0.x)));
            u64 h01 = packbb(lg2(1.0f + ex2(fA0.y)));
            u64 h02 = packbb(lg2(1.0f + ex2(fB0.x)));
            u64 h03 = packbb(lg2(1.0f + ex2(fB0.y)));
            u64 h10 = packbb(lg2(1.0f + ex2(fA1.x)));
            u64 h11 = packbb(lg2(1.0f + ex2(fA1.y)));
            u64 h12 = packbb(lg2(1.0f + ex2(fB1.x)));
            u64 h13 = packbb(lg2(1.0f + ex2(fB1.y)));
            const float* w2j = w2k + jg*64;
            #pragma unroll
            for (int x = 0; x < 8; x++) {
                u64 w0 = *(const u64*)(w2j +  0 + 2*x);
                u64 w1_= *(const u64*)(w2j + 16 + 2*x);
                u64 w2_= *(const u64*)(w2j + 32 + 2*x);
                u64 w3_= *(const u64*)(w2j + 48 + 2*x);
                mu0[x] = fma2(w0, h00, mu0[x]);
                mu0[x] = fma2(w1_, h01, mu0[x]);
                mu0[x] = fma2(w2_, h02, mu0[x]);
                mu0[x] = fma2(w3_, h03, mu0[x]);
                mu1[x] = fma2(w0, h10, mu1[x]);
                mu1[x] = fma2(w1_, h11, mu1[x]);
                mu1[x] = fma2(w2_, h12, mu1[x]);
                mu1[x] = fma2(w3_, h13, mu1[x]);
            }
        }
        u64 neg1 = pack2(-1.0f, -1.0f);
        u64 dd[8];
        float tmp[16];
        load8(tmp, zb); load8(tmp+8, zb+8);
        #pragma unroll
        for (int x = 0; x < 8; x++)
            dd[x] = fma2(mu0[x], neg1, pack2(tmp[2*x], tmp[2*x+1]));
        float maha0 = maha16(dd, sm + OFF_LVT + k*256);
        le0[k] = -0.5f*maha0 - sm[OFF_LDT + k] - 8.0f*LOG2PI;

        load8(tmp, zb+16); load8(tmp+8, zb+24);
        #pragma unroll
        for (int x = 0; x < 8; x++)
            dd[x] = fma2(mu1[x], neg1, pack2(tmp[2*x], tmp[2*x+1]));
        float maha1 = maha16(dd, sm + OFF_LVT + k*256);
        le1[k] = -0.5f*maha1 - sm[OFF_LDT + k] - 8.0f*LOG2PI;
    }

    size_t g0 = (size_t)b*Tt + t0;
    if (t0 != 0) {                       // t=0 handled in snlds_pA
        float m = le0[0];
        #pragma unroll
        for (int k = 1; k < 8; k++) m = fmaxf(m, le0[k]);
        g_m[g0] = m;
        float v[8];
        #pragma unroll
        for (int k = 0; k < 8; k++) v[k] = ex2((le0[k] - m) * LOG2E);
        store8(g_ele + g0*8, v);
    }
    {
        float m = le1[0];
        #pragma unroll
        for (int k = 1; k < 8; k++) m = fmaxf(m, le1[k]);
        g_m[g0+1] = m;
        float v[8];
        #pragma unroll
        for (int k = 0; k < 8; k++) v[k] = ex2((le1[k] - m) * LOG2E);
        store8(g_ele + (g0+1)*8, v);
    }
}

// ---------------- pA: chunk products + in-block superchunk tree (+ t=0 emissions) ----------------
__global__ void __launch_bounds__(256) snlds_pA(const float* __restrict__ z,
                                                const float* __restrict__ init_mean)
{
    __shared__ float sMa[32*64];
    __shared__ float sPa[16*64];
    __shared__ int   sEa[32];
    __shared__ int   sEPa[16];

    int tid = threadIdx.x;
    int gt = blockIdx.x*256 + tid;
    int i = gt & 7;
    int chain = gt >> 3;
    int c = chain & (CC-1);
    int b = chain >> 7;
    int lc = tid >> 3;

    if (blockIdx.x == 0 && tid < 64) {
        int bb = tid;
        const float* zr = z + (size_t)bb*Tt*LDIM;
        float zc[16];
        load8(zc, zr); load8(zc+8, zr+8);
        float le[8];
        #pragma unroll 1
        for (int k = 0; k < 8; k++) {
            float diff[16];
            #pragma unroll
            for (int d = 0; d < 16; d++) diff[d] = zc[d] - init_mean[k*16+d];
            float maha = 0.f;
            #pragma unroll
            for (int d = 0; d < 16; d++) {
                float y = 0.f;
                #pragma unroll
                for (int e = 0; e < 16; e++) y = fmaf(g_Linv0[k*256 + d*16 + e], diff[e], y);
                maha = fmaf(y, y, maha);
            }
            le[k] = -0.5f*maha - g_ld0[k] - 8.0f*LOG2PI;
        }
        float m = le[0];
        #pragma unroll
        for (int k = 1; k < 8; k++) m = fmaxf(m, le[k]);
        g_m[(size_t)bb*Tt] = m;
        float v[8];
        #pragma unroll
        for (int k = 0; k < 8; k++) v[k] = ex2((le[k] - m) * LOG2E);
        store8(g_ele + (size_t)bb*Tt*8, v);
    }

    u64 q2[32];
    #pragma unroll
    for (int x = 0; x < 32; x++) q2[x] = *(const u64*)(g_eQ + 2*x);

    u64 r2[4];
    #pragma unroll
    for (int k2 = 0; k2 < 4; k2++)
        r2[k2] = pack2((i == 2*k2) ? 1.0f : 0.0f, (i == 2*k2+1) ? 1.0f : 0.0f);
    int E = 0;

    const float* eb = g_ele + ((size_t)b*Tt)*8;
    int t0 = c*LC + ((c == 0) ? 1 : 0);
    int t1 = c*LC + LC;

    u64 el2[4];
    #pragma unroll
    for (int k2 = 0; k2 < 4; k2++) el2[k2] = *(const u64*)(eb + (size_t)t0*8 + 2*k2);

    for (int t = t0; t < t1; t++) {
        u64 eln[4];
        int tn = (t+1 < t1) ? (t+1) : t;
        #pragma unroll
        for (int k2 = 0; k2 < 4; k2++) eln[k2] = *(const u64*)(eb + (size_t)tn*8 + 2*k2);

        u64 rb[8];
        #pragma unroll
        for (int x = 0; x < 4; x++) {
            float2 f = unpk(r2[x]);
            rb[2*x] = packbb(f.x); rb[2*x+1] = packbb(f.y);
        }
        u64 n2[4];
        #pragma unroll
        for (int k2 = 0; k2 < 4; k2++) {
            u64 s = mul2(rb[0], q2[0*4 + k2]);
            #pragma unroll
            for (int j = 1; j < 8; j++) s = fma2(rb[j], q2[j*4 + k2], s);
            n2[k2] = mul2(s, el2[k2]);
        }
        float2 f0 = unpk(n2[0]), f1 = unpk(n2[1]), f2 = unpk(n2[2]), f3 = unpk(n2[3]);
        float mx = fmaxf(fmaxf(fmaxf(f0.x,f0.y),fmaxf(f1.x,f1.y)),
                         fmaxf(fmaxf(f2.x,f2.y),fmaxf(f3.x,f3.y)));
        int ib = __float_as_int(mx);
        E += (ib >> 23) - 127;
        u64 scb = packbb(__int_as_float((254 - (ib >> 23)) << 23));
        #pragma unroll
        for (int k2 = 0; k2 < 4; k2++) { r2[k2] = mul2(n2[k2], scb); el2[k2] = eln[k2]; }
    }

    const unsigned FULL = 0xffffffffu;
    int Emax = E;
    Emax = max(Emax, __shfl_xor_sync(FULL, Emax, 1));
    Emax = max(Emax, __shfl_xor_sync(FULL, Emax, 2));
    Emax = max(Emax, __shfl_xor_sync(FULL, Emax, 4));
    int d = E - Emax; if (d < -126) d = -126;
    u64 scb = packbb(__int_as_float((127 + d) << 23));
    #pragma unroll
    for (int k2 = 0; k2 < 4; k2++) {
        u64 val = mul2(r2[k2], scb);
        *(u64*)(g_M + (size_t)chain*64 + i*8 + 2*k2) = val;
        *(u64*)(sMa + lc*64 + i*8 + 2*k2) = val;
    }
    if (i == 0) { g_EM[chain] = Emax; sEa[lc] = Emax; }
    __syncthreads();

    // tree reduce 32 -> 2 superchunks
    for (int e = tid; e < 16*64; e += 256) {
        int m_ = e >> 6, ij = e & 63, ii = ij >> 3, jj = ij & 7;
        const float* L = sMa + (2*m_)*64;
        const float* R = sMa + (2*m_+1)*64;
        float s = 0.f;
        #pragma unroll
        for (int k = 0; k < 8; k++) s = fmaf(L[ii*8+k], R[k*8+jj], s);
        sPa[e] = s;
        if (ij == 0) sEPa[m_] = sEa[2*m_] + sEa[2*m_+1];
    }
    __syncthreads();
    for (int e = tid; e < 8*64; e += 256) {
        int m_ = e >> 6, ij = e & 63, ii = ij >> 3, jj = ij & 7;
        const float* L = sPa + (2*m_)*64;
        const float* R = sPa + (2*m_+1)*64;
        float s = 0.f;
        #pragma unroll
        for (int k = 0; k < 8; k++) s = fmaf(L[ii*8+k], R[k*8+jj], s);
        sMa[e] = s;
        if (ij == 0) sEa[m_] = sEPa[2*m_] + sEPa[2*m_+1];
    }
    __syncthreads();
    for (int e = tid; e < 4*64; e += 256) {
        int m_ = e >> 6, ij = e & 63, ii = ij >> 3, jj = ij & 7;
        const float* L = sMa + (2*m_)*64;
        const float* R = sMa + (2*m_+1)*64;
        float s = 0.f;
        #pragma unroll
        for (int k = 0; k < 8; k++) s = fmaf(L[ii*8+k], R[k*8+jj], s);
        sPa[e] = s;
        if (ij == 0) sEPa[m_] = sEa[2*m_] + sEa[2*m_+1];
    }
    __syncthreads();
    for (int e = tid; e < 2*64; e += 256) {
        int m_ = e >> 6, ij = e & 63, ii = ij >> 3, jj = ij & 7;
        const float* L = sPa + (2*m_)*64;
        const float* R = sPa + (2*m_+1)*64;
        float s = 0.f;
        #pragma unroll
        for (int k = 0; k < 8; k++) s = fmaf(L[ii*8+k], R[k*8+jj], s);
        sMa[e] = s;
        if (ij == 0) sEa[m_] = sEPa[2*m_] + sEPa[2*m_+1];
    }
    __syncthreads();

    if (tid < 64) {
        int m_ = tid >> 5, lane = tid & 31;
        float v0 = sMa[m_*64 + lane], v1 = sMa[m_*64 + 32 + lane];
        float mx = fmaxf(v0, v1);
        #pragma unroll
        for (int off = 16; off >= 1; off >>= 1)
            mx = fmaxf(mx, __shfl_xor_sync(FULL, mx, off));
        int ib = __float_as_int(mx);
        float sc = __int_as_float((254 - (ib >> 23)) << 23);
        int sci = blockIdx.x*2 + m_;
        g_SM[(size_t)sci*64 + lane]      = v0 * sc;
        g_SM[(size_t)sci*64 + 32 + lane] = v1 * sc;
        if (lane == 0) g_ESM[sci] = sEa[m_] + (ib >> 23) - 127;
    }
}

// ---------------- pC: superchunk walk + chunk-boundary propagation + t-recursions ----------------
__global__ void __launch_bounds__(256) snlds_pC()
{
    __shared__ float sVW[16*8];     // per-superchunk entry/exit vectors (2 batches x 8 sc x 8)
    __shared__ int   sEVW[16];
    __shared__ float sBnd[256*8];
    __shared__ int   sEb[256];
    int tid = threadIdx.x;
    int dir = blockIdx.y;
    int bbase = blockIdx.x*2;

    // ---- phase 0: superchunk boundary walk (8 threads per batch, shuffle-parallel) ----
    if (tid < 16) {
        const unsigned M16 = 0xffffu;
        int bl = tid >> 3, k = tid & 7;
        int b = bbase + bl;
        int base = bl*8;               // lane base of this 8-group
        if (dir == 0) {
            // forward: v_{s+1} = v_s . SM[s]; thread k owns v[k], loads column k
            float v = g_epi[k] * g_ele[(size_t)b*Tt*8 + k];
            {
                float mx = v;
                mx = fmaxf(mx, __shfl_xor_sync(M16, mx, 1));
                mx = fmaxf(mx, __shfl_xor_sync(M16, mx, 2));
                mx = fmaxf(mx, __shfl_xor_sync(M16, mx, 4));
                int ib = __float_as_int(mx);
                v *= __int_as_float((254 - (ib >> 23)) << 23);
                int E = (ib >> 23) - 127;
                sVW[(base)*8 + k] = v;     // entry of sc 0
                if (k == 0) sEVW[base] = E;
                // serial walk with double-buffered column loads
                float col[8], coln[8];
                const float* SMb = g_SM + (size_t)(b*NS)*64;
                #pragma unroll
                for (int j = 0; j < 8; j++) col[j] = SMb[j*8 + k];
                for (int s = 0; s < NS-1; s++) {
                    if (s < NS-2) {
                        #pragma unroll
                        for (int j = 0; j < 8; j++) coln[j] = SMb[(s+1)*64 + j*8 + k];
                    }
                    float nv = 0.f;
                    #pragma unroll
                    for (int j = 0; j < 8; j++)
                        nv = fmaf(__shfl_sync(M16, v, base + j), col[j], nv);
                    float mx2 = nv;
                    mx2 = fmaxf(mx2, __shfl_xor_sync(M16, mx2, 1));
                    mx2 = fmaxf(mx2, __shfl_xor_sync(M16, mx2, 2));
                    mx2 = fmaxf(mx2, __shfl_xor_sync(M16, mx2, 4));
                    int ib2 = __float_as_int(mx2);
                    v = nv * __int_as_float((254 - (ib2 >> 23)) << 23);
                    E += (ib2 >> 23) - 127 + g_ESM[b*NS + s];
                    sVW[(base + s + 1)*8 + k] = v;
                    if (k == 0) sEVW[base + s + 1] = E;
                    #pragma unroll
                    for (int j = 0; j < 8; j++) col[j] = coln[j];
                }
            }
        } else {
            // backward: w_{s-1} = SM[s] . w_s; thread k owns w[k], loads row k
            float w = 1.0f;
            int F = 0;
            sVW[(base + NS-1)*8 + k] = w;
            if (k == 0) sEVW[base + NS-1] = 0;
            float row[8], rown[8];
            const float* SMb = g_SM + (size_t)(b*NS)*64;
            load8(row, SMb + (NS-1)*64 + k*8);
            for (int s = NS-1; s >= 1; s--) {
                if (s > 1) load8(rown, SMb + (s-1)*64 + k*8);
                float nw = 0.f;
                #pragma unroll
                for (int j = 0; j < 8; j++)
                    nw = fmaf(row[j], __shfl_sync(M16, w, base + j), nw);
                float mx2 = nw;
                mx2 = fmaxf(mx2, __shfl_xor_sync(M16, mx2, 1));
                mx2 = fmaxf(mx2, __shfl_xor_sync(M16, mx2, 2));
                mx2 = fmaxf(mx2, __shfl_xor_sync(M16, mx2, 4));
                int ib2 = __float_as_int(mx2);
                w = nw * __int_as_float((254 - (ib2 >> 23)) << 23);
                F += (ib2 >> 23) - 127 + g_ESM[b*NS + s];
                sVW[(base + s - 1)*8 + k] = w;
                if (k == 0) sEVW[base + s - 1] = F;
                #pragma unroll
                for (int j = 0; j < 8; j++) row[j] = rown[j];
            }
        }
    }
    __syncthreads();

    // ---- phase A: 16 walkers propagate chunk boundaries within superchunks ----
    if (tid < 16) {
        int bl = tid >> 3, s = tid & 7;
        int b = bbase + bl;
        int c0 = b*CC + s*SCn;
        if (dir == 0) {
            float v[8];
            load8(v, sVW + (size_t)(bl*8 + s)*8);
            int E = sEVW[bl*8 + s];
            for (int cc = 0; cc < SCn; cc++) {
                store8(sBnd + (size_t)(bl*128 + s*16 + cc)*8, v);
                sEb[bl*128 + s*16 + cc] = E;
                if (cc < SCn-1) {
                    float M[64];
                    #pragma unroll
                    for (int x = 0; x < 8; x++) load8(M + x*8, g_M + (size_t)(c0+cc)*64 + x*8);
                    float n[8];
                    #pragma unroll
                    for (int k = 0; k < 8; k++) {
                        float sv = v[0]*M[0*8+k];
                        #pragma unroll
                        for (int j = 1; j < 8; j++) sv = fmaf(v[j], M[j*8+k], sv);
                        n[k] = sv;
                    }
                    E += rescale8(n) + g_EM[c0+cc];
                    #pragma unroll
                    for (int k = 0; k < 8; k++) v[k] = n[k];
                }
            }
        } else {
            float w[8];
            load8(w, sVW + (size_t)(bl*8 + s)*8);
            int F = sEVW[bl*8 + s];
            for (int cc = SCn-1; cc >= 0; cc--) {
                store8(sBnd + (size_t)(bl*128 + s*16 + cc)*8, w);
                sEb[bl*128 + s*16 + cc] = F;
                if (cc > 0) {
                    float M[64];
                    #pragma unroll
                    for (int x = 0; x < 8; x++) load8(M + x*8, g_M + (size_t)(c0+cc)*64 + x*8);
                    float n[8];
                    #pragma unroll
                    for (int i = 0; i < 8; i++) {
                        float sv = M[i*8+0]*w[0];
                        #pragma unroll
                        for (int k = 1; k < 8; k++) sv = fmaf(M[i*8+k], w[k], sv);
                        n[i] = sv;
                    }
                    F += rescale8(n) + g_EM[c0+cc];
                    #pragma unroll
                    for (int k = 0; k < 8; k++) w[k] = n[k];
                }
            }
        }
    }
    __syncthreads();

    // ---- phase B: 256 chains = 2 batches x 128 chunks ----
    int bl = tid >> 7;
    int c  = tid & 127;
    int b  = bbase + bl;

    u64 q2[32];
    #pragma unroll
    for (int x = 0; x < 32; x++) q2[x] = *(const u64*)(g_eQ + 2*x);

    const float* eb = g_ele + (size_t)b*Tt*8;
    const float* bnd = sBnd + (size_t)(bl*128 + c)*8;

    if (dir == 0) {
        u64 a2[4];
        #pragma unroll
        for (int k2 = 0; k2 < 4; k2++) a2[k2] = *(const u64*)(bnd + 2*k2);
        int E = sEb[bl*128 + c];
        float* Ad = g_A + (size_t)b*Tt*8;
        int t0 = c*LC;
        if (c == 0) {
            float2 f0 = unpk(a2[0]), f1 = unpk(a2[1]), f2 = unpk(a2[2]), f3 = unpk(a2[3]);
            #pragma unroll
            for (int k2 = 0; k2 < 4; k2++) *(u64*)(Ad + 2*k2) = a2[k2];
            g_sig[b*Tt] = f0.x+f0.y+f1.x+f1.y+f2.x+f2.y+f3.x+f3.y;
            g_E[b*Tt] = E;
            t0 = 1;
        }
        int t1 = c*LC + LC;
        u64 el2[4];
        #pragma unroll
        for (int k2 = 0; k2 < 4; k2++) el2[k2] = *(const u64*)(eb + (size_t)t0*8 + 2*k2);
        for (int t = t0; t < t1; t++) {
            u64 eln[4];
            int tn = (t+1 < t1) ? (t+1) : t;
            #pragma unroll
            for (int k2 = 0; k2 < 4; k2++) eln[k2] = *(const u64*)(eb + (size_t)tn*8 + 2*k2);
            u64 ab[8];
            #pragma unroll
            for (int x = 0; x < 4; x++) {
                float2 f = unpk(a2[x]);
                ab[2*x] = packbb(f.x); ab[2*x+1] = packbb(f.y);
            }
            u64 n2[4];
            #pragma unroll
            for (int k2 = 0; k2 < 4; k2++) {
                u64 s = mul2(ab[0], q2[0*4 + k2]);
                #pragma unroll
                for (int j = 1; j < 8; j++) s = fma2(ab[j], q2[j*4 + k2], s);
                n2[k2] = mul2(s, el2[k2]);
            }
            float2 f0 = unpk(n2[0]), f1 = unpk(n2[1]), f2 = unpk(n2[2]), f3 = unpk(n2[3]);
            float mx = fmaxf(fmaxf(fmaxf(f0.x,f0.y),fmaxf(f1.x,f1.y)),
                             fmaxf(fmaxf(f2.x,f2.y),fmaxf(f3.x,f3.y)));
            int ib = __float_as_int(mx);
            E += (ib >> 23) - 127;
            float sc = __int_as_float((254 - (ib >> 23)) << 23);
            u64 scb = packbb(sc);
            #pragma unroll
            for (int k2 = 0; k2 < 4; k2++) {
                a2[k2] = mul2(n2[k2], scb);
                el2[k2] = eln[k2];
                *(u64*)(Ad + (size_t)t*8 + 2*k2) = a2[k2];
            }
            g_sig[b*Tt + t] = (f0.x+f0.y+f1.x+f1.y+f2.x+f2.y+f3.x+f3.y) * sc;
            g_E[b*Tt + t] = E;
        }
    } else {
        u64 w2[4];
        #pragma unroll
        for (int j2 = 0; j2 < 4; j2++) w2[j2] = *(const u64*)(bnd + 2*j2);
        int F = sEb[bl*128 + c];
        float* Bd = g_Bv + (size_t)b*Tt*8;
        int thi = c*LC + LC - 1;
        int lo  = c*LC;
        #pragma unroll
        for (int j2 = 0; j2 < 4; j2++) *(u64*)(Bd + (size_t)thi*8 + 2*j2) = w2[j2];
        g_F[b*Tt + thi] = F;
        u64 el2[4];
        #pragma unroll
        for (int j2 = 0; j2 < 4; j2++) el2[j2] = *(const u64*)(eb + (size_t)thi*8 + 2*j2);
        for (int t = thi - 1; t >= lo; t--) {
            u64 eln[4];
            int tn = (t > lo) ? t : lo;
            #pragma unroll
            for (int j2 = 0; j2 < 4; j2++) eln[j2] = *(const u64*)(eb + (size_t)tn*8 + 2*j2);
            u64 s2[4];
            #pragma unroll
            for (int j2 = 0; j2 < 4; j2++) s2[j2] = mul2(el2[j2], w2[j2]);
            float n[8];
            #pragma unroll
            for (int i = 0; i < 8; i++) {
                u64 acc = mul2(q2[i*4 + 0], s2[0]);
                acc = fma2(q2[i*4 + 1], s2[1], acc);
                acc = fma2(q2[i*4 + 2], s2[2], acc);
                acc = fma2(q2[i*4 + 3], s2[3], acc);
                float2 f = unpk(acc);
                n[i] = f.x + f.y;
            }
            F += rescale8(n);
            #pragma unroll
            for (int j2 = 0; j2 < 4; j2++) { w2[j2] = pack2(n[2*j2], n[2*j2+1]); el2[j2] = eln[j2]; }
            store8(Bd + (size_t)t*8, n);
            g_F[b*Tt + t] = F;
        }
    }
}

// ---------------- outputs: gamma, paired, log_Z ----------------
__global__ void __launch_bounds__(256) snlds_out(float* __restrict__ out)
{
    const unsigned FULL = 0xffffffffu;
    __shared__ float seQ[64];
    int tid = threadIdx.x;
    if (tid < 64) seQ[tid] = g_eQ[tid];
    __syncthreads();

    int gidx = blockIdx.x*32 + (tid >> 3);
    int i    = tid & 7;
    int t    = gidx & (Tt-1);
    int b    = gidx >> 11;

    float ai = g_A [(size_t)gidx*8 + i];
    float bi = g_Bv[(size_t)gidx*8 + i];
    float pr = ai * bi;
    float G = pr;
    G += __shfl_xor_sync(FULL, G, 1);
    G += __shfl_xor_sync(FULL, G, 2);
    G += __shfl_xor_sync(FULL, G, 4);
    float rG = 1.0f / G;
    out[(size_t)gidx*8 + i] = pr * rG;                  // gamma

    if (i == 0) {                                       // log_Z
        float lz;
        if (t == 0) lz = (lg2(g_sig[gidx]) + (float)g_E[gidx]) * LN2F + g_m[gidx];
        else        lz = (lg2(g_sig[gidx]) - lg2(g_sig[gidx-1])
                          + (float)(g_E[gidx] - g_E[gidx-1])) * LN2F + g_m[gidx];
        out[(size_t)GSZ + PSZ + gidx] = lz;
    }

    // paired
    int gn = (t < Tt-1) ? (gidx + 1) : gidx;
    float bj = g_Bv [(size_t)gn*8 + i];
    float ej = g_ele[(size_t)gn*8 + i];
    float cj = bj * ej;
    int dF = g_F[gidx] - g_F[gn];
    int sb = 127 - dF; if (sb < 1) sb = 1; if (sb > 254) sb = 254;
    float pnorm = rG * __int_as_float(sb << 23);

    int baseLane = tid & 24;
    float cb[8];
    #pragma unroll
    for (int j = 0; j < 8; j++) cb[j] = __shfl_sync(FULL, cj, baseLane + j);

    if (t < Tt-1) {
        float eA = ai * pnorm;
        size_t pbase = (size_t)GSZ + ((size_t)(b*(Tt-1) + t))*64 + (size_t)i*8;
        float4 p0, p1;
        p0.x = eA * seQ[i*8+0] * cb[0];
        p0.y = eA * seQ[i*8+1] * cb[1];
        p0.z = eA * seQ[i*8+2] * cb[2];
        p0.w = eA * seQ[i*8+3] * cb[3];
        p1.x = eA * seQ[i*8+4] * cb[4];
        p1.y = eA * seQ[i*8+5] * cb[5];
        p1.z = eA * seQ[i*8+6] * cb[6];
        p1.w = eA * seQ[i*8+7] * cb[7];
        *(float4*)(out + pbase)     = p0;
        *(float4*)(out + pbase + 4) = p1;
    }
}

extern "C" void kernel_launch(void* const* d_in, const int* in_sizes, int n_in,
                              void* d_out, int out_size) {
    const float* z         = (const float*)d_in[0];
    const float* pi        = (const float*)d_in[1];
    const float* Q         = (const float*)d_in[2];
    const float* init_mean = (const float*)d_in[3];
    const float* init_cov  = (const float*)d_in[4];
    const float* covs      = (const float*)d_in[5];
    const float* W1        = (const float*)d_in[6];
    const float* b1        = (const float*)d_in[7];
    const float* W2        = (const float*)d_in[8];
    const float* b2        = (const float*)d_in[9];
    float* out = (float*)d_out;

    cudaFuncSetAttribute(snlds_emis, cudaFuncAttributeMaxDynamicSharedMemorySize, EMIS_SMEM_BYTES);

    snlds_prep<<<1, 256>>>(pi, Q, init_cov, covs);
    snlds_emis<<<(Bb*Tt/2)/128, 128, EMIS_SMEM_BYTES>>>(z, W1, b1, W2, b2);
    snlds_pA<<<(Bb*CC*8)/256, 256>>>(z, init_mean);
    snlds_pC<<<dim3(Bb/2, 2), 256>>>();
    snlds_out<<<(Bb*Tt)/32, 256>>>(out);
}

// round 14
// speedup vs baseline: 1.0073x; 1.0073x over previous
#include <cuda_runtime.h>
#include <math.h>
#include <stdint.h>

#define Bb   64
#define Tt   2048
#define LDIM 16
#define HDIM 64
#define Kk   8
#define LC   16
#define CC   128             // Tt / LC
#define SCn  16              // chunks per superchunk
#define NS   8               // superchunks per batch = CC/SCn

#define LOG2E  1.4426950408889634f
#define LN2F   0.6931471805599453f
#define LOG2PI 1.8378770664093453f

#define GSZ  (Bb*Tt*Kk)            // gamma elements
#define PSZ  (Bb*(Tt-1)*Kk*Kk)     // paired elements

typedef unsigned long long u64;

// ---------------- f32x2 / MUFU helpers ----------------
__device__ __forceinline__ u64 fma2(u64 a, u64 b, u64 c){
    u64 d; asm("fma.rn.f32x2 %0, %1, %2, %3;" : "=l"(d) : "l"(a), "l"(b), "l"(c)); return d;
}
__device__ __forceinline__ u64 mul2(u64 a, u64 b){
    u64 d; asm("mul.rn.f32x2 %0, %1, %2;" : "=l"(d) : "l"(a), "l"(b)); return d;
}
__device__ __forceinline__ u64 packbb(float x){
    u64 d; asm("mov.b64 %0, {%1, %1};" : "=l"(d) : "f"(x)); return d;
}
__device__ __forceinline__ u64 pack2(float x, float y){
    u64 d; asm("mov.b64 %0, {%1, %2};" : "=l"(d) : "f"(x), "f"(y)); return d;
}
__device__ __forceinline__ float2 unpk(u64 u){
    float2 f; asm("mov.b64 {%0, %1}, %2;" : "=f"(f.x), "=f"(f.y) : "l"(u)); return f;
}
__device__ __forceinline__ float ex2(float x){ float r; asm("ex2.approx.ftz.f32 %0, %1;" : "=f"(r) : "f"(x)); return r; }
__device__ __forceinline__ float lg2(float x){ float r; asm("lg2.approx.f32 %0, %1;" : "=f"(r) : "f"(x)); return r; }

// ---------------- scratch ----------------
__device__ __align__(16) float g_ele[Bb*Tt*Kk];   // exp(le - m_t)
__device__ float g_m  [Bb*Tt];                    // m_t = max_k le
__device__ __align__(16) float g_A  [Bb*Tt*Kk];   // scaled forward
__device__ __align__(16) float g_Bv [Bb*Tt*Kk];   // scaled backward
__device__ float g_sig[Bb*Tt];                    // sum_k a-hat_t
__device__ int   g_E  [Bb*Tt];
__device__ int   g_F  [Bb*Tt];
__device__ __align__(16) float g_M  [Bb*CC*64];   // chunk matrices
__device__ int   g_EM [Bb*CC];
__device__ __align__(16) float g_SM [Bb*NS*64];   // superchunk matrices
__device__ int   g_ESM[Bb*NS];
__device__ __align__(16) float g_eQ [64];
__device__ float g_epi[8];
__device__ float g_Qlog[64];
__device__ float g_logpi[8];
__device__ float g_Linv0[Kk*LDIM*LDIM];
__device__ float g_LinvT[Kk*LDIM*LDIM];
__device__ float g_ld0[Kk];
__device__ float g_ldT[Kk];

__device__ __forceinline__ int rescale8(float* v) {
    float mx = v[0];
    #pragma unroll
    for (int k = 1; k < 8; k++) mx = fmaxf(mx, v[k]);
    int ib = __float_as_int(mx);
    int ee = (ib >> 23) - 127;
    float sc = __int_as_float((254 - (ib >> 23)) << 23);
    #pragma unroll
    for (int k = 0; k < 8; k++) v[k] *= sc;
    return ee;
}

__device__ __forceinline__ void load8(float* dst, const float* src) {
    float4 a = *(const float4*)src;
    float4 b = *(const float4*)(src + 4);
    dst[0]=a.x; dst[1]=a.y; dst[2]=a.z; dst[3]=a.w;
    dst[4]=b.x; dst[5]=b.y; dst[6]=b.z; dst[7]=b.w;
}
__device__ __forceinline__ void store8(float* dst, const float* v) {
    *(float4*)dst       = make_float4(v[0], v[1], v[2], v[3]);
    *(float4*)(dst + 4) = make_float4(v[4], v[5], v[6], v[7]);
}

// ---------------- prep ----------------
__global__ void snlds_prep(const float* __restrict__ pi,
                           const float* __restrict__ Q,
                           const float* __restrict__ init_cov,
                           const float* __restrict__ covs)
{
    __shared__ float S[16][256];
    int tid = threadIdx.x;         // 256 threads

    for (int e = tid; e < 4096; e += 256) {
        int m  = e >> 8;
        int ij = e & 255;
        int i  = ij >> 4, j = ij & 15;
        const float* C = (m < 8) ? (init_cov + m*256) : (covs + (m-8)*256);
        float s = (i == j) ? 1e-6f : 0.0f;
        #pragma unroll
        for (int d = 0; d < 16; d++) s = fmaf(C[i*16+d], C[j*16+d], s);
        S[m][ij] = s;
    }
    __syncthreads();

    int m = tid >> 4, r = tid & 15;
    for (int kk = 0; kk < 16; kk++) {
        if (r == kk) {
            float s = S[m][kk*16+kk];
            for (int e2 = 0; e2 < kk; e2++) { float v = S[m][kk*16+e2]; s -= v*v; }
            S[m][kk*16+kk] = sqrtf(s);
        }
        __syncthreads();
        if (r > kk) {
            float s = S[m][r*16+kk];
            for (int e2 = 0; e2 < kk; e2++) s -= S[m][r*16+e2]*S[m][kk*16+e2];
            S[m][r*16+kk] = s / S[m][kk*16+kk];
        }
        __syncthreads();
    }

    if (r == 0) {
        float s = 0.f;
        for (int d = 0; d < 16; d++) s += logf(S[m][d*16+d]);
        if (m < 8) g_ld0[m] = s; else g_ldT[m-8] = s;
    }

    {
        int c = r;
        float x[16];
        #pragma unroll
        for (int i2 = 0; i2 < 16; i2++) x[i2] = 0.f;
        for (int i2 = c; i2 < 16; i2++) {
            float s = (i2 == c) ? 1.0f : 0.0f;
            for (int e2 = c; e2 < i2; e2++) s -= S[m][i2*16+e2]*x[e2];
            x[i2] = s / S[m][i2*16+i2];
        }
        float* dst = (m < 8) ? (g_Linv0 + m*256) : (g_LinvT + (m-8)*256);
        for (int i2 = 0; i2 < 16; i2++) dst[i2*16 + c] = x[i2];
    }

    if (tid < 8) {
        float mx = -1e30f;
        for (int j = 0; j < 8; j++) mx = fmaxf(mx, Q[tid*8+j]);
        float se = 0.f;
        for (int j = 0; j < 8; j++) se += expf(Q[tid*8+j]-mx);
        float l = mx + logf(se);
        for (int j = 0; j < 8; j++) g_Qlog[tid*8+j] = Q[tid*8+j] - l;
    }
    if (tid == 8) {
        float mx = -1e30f;
        for (int j = 0; j < 8; j++) mx = fmaxf(mx, pi[j]);
        float se = 0.f;
        for (int j = 0; j < 8; j++) se += expf(pi[j]-mx);
        float l = mx + logf(se);
        for (int j = 0; j < 8; j++) g_logpi[j] = pi[j] - l;
    }
    __syncthreads();
    if (tid < 64) g_eQ[tid] = expf(g_Qlog[tid]);
    if (tid < 8)  g_epi[tid] = expf(g_logpi[tid]);
}

// ---------------- emissions: t>=1, 2 t per thread, 74.5KB smem ----------------
#define OFF_W1   0            // [k][d][j] * LOG2E  8192
#define OFF_W2   8192         // [k][j][d] * LN2F   8192
#define OFF_LVT  16384        // [k][e][d]          2048
#define OFF_B1   18432        // [k][j] * LOG2E     512
#define OFF_B2   18944        // [k][d]             128
#define OFF_LDT  19072        // 8
#define EMIS_SMEM_FLOATS 19080
#define EMIS_SMEM_BYTES  (EMIS_SMEM_FLOATS*4)

__device__ __forceinline__ float maha16(const u64* dd, const float* LT) {
    u64 dbb[16];
    #pragma unroll
    for (int x = 0; x < 8; x++) {
        float2 f = unpk(dd[x]);
        dbb[2*x]   = packbb(f.x);
        dbb[2*x+1] = packbb(f.y);
    }
    u64 y2[8];
    #pragma unroll
    for (int x = 0; x < 8; x++) y2[x] = 0ull;
    #pragma unroll
    for (int e = 0; e < 16; e++) {
        #pragma unroll
        for (int x = 0; x < 8; x++)
            y2[x] = fma2(*(const u64*)(LT + e*16 + 2*x), dbb[e], y2[x]);
    }
    u64 m2 = 0ull;
    #pragma unroll
    for (int x = 0; x < 8; x++) m2 = fma2(y2[x], y2[x], m2);
    float2 mm = unpk(m2);
    return mm.x + mm.y;
}

__global__ void __launch_bounds__(128) snlds_emis(const float* __restrict__ z,
                                                  const float* __restrict__ W1,
                                                  const float* __restrict__ b1,
                                                  const float* __restrict__ W2,
                                                  const float* __restrict__ b2)
{
    extern __shared__ float sm[];
    int tx = threadIdx.x;

    for (int i = tx; i < 8192; i += 128) {
        int k = i >> 10, rem = i & 1023;
        int j = rem >> 4, d = rem & 15;
        sm[OFF_W1 + k*1024 + d*64 + j] = LOG2E * W1[i];
        int d2 = rem >> 6, j2 = rem & 63;
        sm[OFF_W2 + k*1024 + j2*16 + d2] = LN2F * W2[i];
    }
    for (int i = tx; i < 2048; i += 128) {
        int k = i >> 8, rem = i & 255;
        int d = rem >> 4, e = rem & 15;
        sm[OFF_LVT + k*256 + e*16 + d] = g_LinvT[i];
    }
    for (int i = tx; i < 512; i += 128) sm[OFF_B1 + i] = LOG2E * b1[i];
    if (tx < 128) sm[OFF_B2 + tx] = b2[tx];
    if (tx < 8) sm[OFF_LDT + tx] = g_ldT[tx];
    __syncthreads();

    int p = blockIdx.x*128 + tx;         // 65536 t-pairs
    int b = p >> 10;
    int t0 = (p & 1023) << 1;
    const float* zb = z + ((size_t)b*Tt + t0)*LDIM;

    u64 v0bb[16], v1bb[16];
    {
        float tmp[16];
        const float* z0 = (p == 0) ? zb : (zb - LDIM);   // OOB clamp only
        load8(tmp, z0); load8(tmp+8, z0+8);
        #pragma unroll
        for (int d = 0; d < 16; d++) v0bb[d] = packbb(tmp[d]);
        load8(tmp, zb); load8(tmp+8, zb+8);
        #pragma unroll
        for (int d = 0; d < 16; d++) v1bb[d] = packbb(tmp[d]);
    }

    float le0[8], le1[8];

    #pragma unroll 1
    for (int k = 0; k < 8; k++) {
        const float* w1k = sm + OFF_W1 + k*1024;
        const float* w2k = sm + OFF_W2 + k*1024;
        u64 mu0[8], mu1[8];
        #pragma unroll
        for (int x = 0; x < 8; x++) {
            u64 bp = *(const u64*)(sm + OFF_B2 + k*16 + 2*x);
            mu0[x] = bp; mu1[x] = bp;
        }
        #pragma unroll 1
        for (int jg = 0; jg < 16; jg++) {
            const float* w1j = w1k + jg*4;
            u64 bA = *(const u64*)(sm + OFF_B1 + k*64 + jg*4);
            u64 bB = *(const u64*)(sm + OFF_B1 + k*64 + jg*4 + 2);
            u64 aA0 = bA, aA1 = bA, aB0 = bB, aB1 = bB;
            #pragma unroll
            for (int d = 0; d < 16; d++) {
                u64 wA = *(const u64*)(w1j + d*64);
                u64 wB = *(const u64*)(w1j + d*64 + 2);
                aA0 = fma2(wA, v0bb[d], aA0);
                aA1 = fma2(wA, v1bb[d], aA1);
                aB0 = fma2(wB, v0bb[d], aB0);
                aB1 = fma2(wB, v1bb[d], aB1);
            }
            float2 fA0 = unpk(aA0), fB0 = unpk(aB0), fA1 = unpk(aA1), fB1 = unpk(aB1);
            u64 h00 = packbb(lg2(1.0f + ex2(fA0.x)));
            u64 h01 = packbb(lg2(1.0f + ex2(fA0.y)));
            u64 h02 = packbb(lg2(1.0f + ex2(fB0.x)));
            u64 h03 = packbb(lg2(1.0f + ex2(fB0.y)));
            u64 h10 = packbb(lg2(1.0f + ex2(fA1.x)));
            u64 h11 = packbb(lg2(1.0f + ex2(fA1.y)));
            u64 h12 = packbb(lg2(1.0f + ex2(fB1.x)));
            u64 h13 = packbb(lg2(1.0f + ex2(fB1.y)));
            const float* w2j = w2k + jg*64;
            #pragma unroll
            for (int x = 0; x < 8; x++) {
                u64 w0 = *(const u64*)(w2j +  0 + 2*x);
                u64 w1_= *(const u64*)(w2j + 16 + 2*x);
                u64 w2_= *(const u64*)(w2j + 32 + 2*x);
                u64 w3_= *(const u64*)(w2j + 48 + 2*x);
                mu0[x] = fma2(w0, h00, mu0[x]);
                mu0[x] = fma2(w1_, h01, mu0[x]);
                mu0[x] = fma2(w2_, h02, mu0[x]);
                mu0[x] = fma2(w3_, h03, mu0[x]);
                mu1[x] = fma2(w0, h10, mu1[x]);
                mu1[x] = fma2(w1_, h11, mu1[x]);
                mu1[x] = fma2(w2_, h12, mu1[x]);
                mu1[x] = fma2(w3_, h13, mu1[x]);
            }
        }
        u64 neg1 = pack2(-1.0f, -1.0f);
        u64 dd[8];
        float tmp[16];
        load8(tmp, zb); load8(tmp+8, zb+8);
        #pragma unroll
        for (int x = 0; x < 8; x++)
            dd[x] = fma2(mu0[x], neg1, pack2(tmp[2*x], tmp[2*x+1]));
        float maha0 = maha16(dd, sm + OFF_LVT + k*256);
        le0[k] = -0.5f*maha0 - sm[OFF_LDT + k] - 8.0f*LOG2PI;

        load8(tmp, zb+16); load8(tmp+8, zb+24);
        #pragma unroll
        for (int x = 0; x < 8; x++)
            dd[x] = fma2(mu1[x], neg1, pack2(tmp[2*x], tmp[2*x+1]));
        float maha1 = maha16(dd, sm + OFF_LVT + k*256);
        le1[k] = -0.5f*maha1 - sm[OFF_LDT + k] - 8.0f*LOG2PI;
    }

    size_t g0 = (size_t)b*Tt + t0;
    if (t0 != 0) {                       // t=0 handled in snlds_pA
        float m = le0[0];
        #pragma unroll
        for (int k = 1; k < 8; k++) m = fmaxf(m, le0[k]);
        g_m[g0] = m;
        float v[8];
        #pragma unroll
        for (int k = 0; k < 8; k++) v[k] = ex2((le0[k] - m) * LOG2E);
        store8(g_ele + g0*8, v);
    }
    {
        float m = le1[0];
        #pragma unroll
        for (int k = 1; k < 8; k++) m = fmaxf(m, le1[k]);
        g_m[g0+1] = m;
        float v[8];
        #pragma unroll
        for (int k = 0; k < 8; k++) v[k] = ex2((le1[k] - m) * LOG2E);
        store8(g_ele + (g0+1)*8, v);
    }
}

// ---------------- pA: chunk products + in-block superchunk tree (+ t=0 emissions) ----------------
__global__ void __launch_bounds__(256) snlds_pA(const float* __restrict__ z,
                                                const float* __restrict__ init_mean)
{
    __shared__ float sMa[32*64];
    __shared__ float sPa[16*64];
    __shared__ int   sEa[32];
    __shared__ int   sEPa[16];

    int tid = threadIdx.x;
    int gt = blockIdx.x*256 + tid;
    int i = gt & 7;
    int chain = gt >> 3;
    int c = chain & (CC-1);
    int b = chain >> 7;
    int lc = tid >> 3;

    if (blockIdx.x == 0 && tid < 64) {
        int bb = tid;
        const float* zr = z + (size_t)bb*Tt*LDIM;
        float zc[16];
        load8(zc, zr); load8(zc+8, zr+8);
        float le[8];
        #pragma unroll 1
        for (int k = 0; k < 8; k++) {
            float diff[16];
            #pragma unroll
            for (int d = 0; d < 16; d++) diff[d] = zc[d] - init_mean[k*16+d];
            float maha = 0.f;
            #pragma unroll
            for (int d = 0; d < 16; d++) {
                float y = 0.f;
                #pragma unroll
                for (int e = 0; e < 16; e++) y = fmaf(g_Linv0[k*256 + d*16 + e], diff[e], y);
                maha = fmaf(y, y, maha);
            }
            le[k] = -0.5f*maha - g_ld0[k] - 8.0f*LOG2PI;
        }
        float m = le[0];
        #pragma unroll
        for (int k = 1; k < 8; k++) m = fmaxf(m, le[k]);
        g_m[(size_t)bb*Tt] = m;
        float v[8];
        #pragma unroll
        for (int k = 0; k < 8; k++) v[k] = ex2((le[k] - m) * LOG2E);
        store8(g_ele + (size_t)bb*Tt*8, v);
    }

    u64 q2[32];
    #pragma unroll
    for (int x = 0; x < 32; x++) q2[x] = *(const u64*)(g_eQ + 2*x);

    u64 r2[4];
    #pragma unroll
    for (int k2 = 0; k2 < 4; k2++)
        r2[k2] = pack2((i == 2*k2) ? 1.0f : 0.0f, (i == 2*k2+1) ? 1.0f : 0.0f);
    int E = 0;

    const float* eb = g_ele + ((size_t)b*Tt)*8;
    int t0 = c*LC + ((c == 0) ? 1 : 0);
    int t1 = c*LC + LC;

    u64 el2[4];
    #pragma unroll
    for (int k2 = 0; k2 < 4; k2++) el2[k2] = *(const u64*)(eb + (size_t)t0*8 + 2*k2);

    for (int t = t0; t < t1; t++) {
        u64 eln[4];
        int tn = (t+1 < t1) ? (t+1) : t;
        #pragma unroll
        for (int k2 = 0; k2 < 4; k2++) eln[k2] = *(const u64*)(eb + (size_t)tn*8 + 2*k2);

        u64 rb[8];
        #pragma unroll
        for (int x = 0; x < 4; x++) {
            float2 f = unpk(r2[x]);
            rb[2*x] = packbb(f.x); rb[2*x+1] = packbb(f.y);
        }
        u64 n2[4];
        #pragma unroll
        for (int k2 = 0; k2 < 4; k2++) {
            u64 s = mul2(rb[0], q2[0*4 + k2]);
            #pragma unroll
            for (int j = 1; j < 8; j++) s = fma2(rb[j], q2[j*4 + k2], s);
            n2[k2] = mul2(s, el2[k2]);
        }
        float2 f0 = unpk(n2[0]), f1 = unpk(n2[1]), f2 = unpk(n2[2]), f3 = unpk(n2[3]);
        float mx = fmaxf(fmaxf(fmaxf(f0.x,f0.y),fmaxf(f1.x,f1.y)),
                         fmaxf(fmaxf(f2.x,f2.y),fmaxf(f3.x,f3.y)));
        int ib = __float_as_int(mx);
        E += (ib >> 23) - 127;
        u64 scb = packbb(__int_as_float((254 - (ib >> 23)) << 23));
        #pragma unroll
        for (int k2 = 0; k2 < 4; k2++) { r2[k2] = mul2(n2[k2], scb); el2[k2] = eln[k2]; }
    }

    const unsigned FULL = 0xffffffffu;
    int Emax = E;
    Emax = max(Emax, __shfl_xor_sync(FULL, Emax, 1));
    Emax = max(Emax, __shfl_xor_sync(FULL, Emax, 2));
    Emax = max(Emax, __shfl_xor_sync(FULL, Emax, 4));
    int d = E - Emax; if (d < -126) d = -126;
    u64 scb = packbb(__int_as_float((127 + d) << 23));
    #pragma unroll
    for (int k2 = 0; k2 < 4; k2++) {
        u64 val = mul2(r2[k2], scb);
        *(u64*)(g_M + (size_t)chain*64 + i*8 + 2*k2) = val;
        *(u64*)(sMa + lc*64 + i*8 + 2*k2) = val;
    }
    if (i == 0) { g_EM[chain] = Emax; sEa[lc] = Emax; }
    __syncthreads();

    // tree reduce 32 -> 2 superchunks
    for (int e = tid; e < 16*64; e += 256) {
        int m_ = e >> 6, ij = e & 63, ii = ij >> 3, jj = ij & 7;
        const float* L = sMa + (2*m_)*64;
        const float* R = sMa + (2*m_+1)*64;
        float s = 0.f;
        #pragma unroll
        for (int k = 0; k < 8; k++) s = fmaf(L[ii*8+k], R[k*8+jj], s);
        sPa[e] = s;
        if (ij == 0) sEPa[m_] = sEa[2*m_] + sEa[2*m_+1];
    }
    __syncthreads();
    for (int e = tid; e < 8*64; e += 256) {
        int m_ = e >> 6, ij = e & 63, ii = ij >> 3, jj = ij & 7;
        const float* L = sPa + (2*m_)*64;
        const float* R = sPa + (2*m_+1)*64;
        float s = 0.f;
        #pragma unroll
        for (int k = 0; k < 8; k++) s = fmaf(L[ii*8+k], R[k*8+jj], s);
        sMa[e] = s;
        if (ij == 0) sEa[m_] = sEPa[2*m_] + sEPa[2*m_+1];
    }
    __syncthreads();
    for (int e = tid; e < 4*64; e += 256) {
        int m_ = e >> 6, ij = e & 63, ii = ij >> 3, jj = ij & 7;
        const float* L = sMa + (2*m_)*64;
        const float* R = sMa + (2*m_+1)*64;
        float s = 0.f;
        #pragma unroll
        for (int k = 0; k < 8; k++) s = fmaf(L[ii*8+k], R[k*8+jj], s);
        sPa[e] = s;
        if (ij == 0) sEPa[m_] = sEa[2*m_] + sEa[2*m_+1];
    }
    __syncthreads();
    for (int e = tid; e < 2*64; e += 256) {
        int m_ = e >> 6, ij = e & 63, ii = ij >> 3, jj = ij & 7;
        const float* L = sPa + (2*m_)*64;
        const float* R = sPa + (2*m_+1)*64;
        float s = 0.f;
        #pragma unroll
        for (int k = 0; k < 8; k++) s = fmaf(L[ii*8+k], R[k*8+jj], s);
        sMa[e] = s;
        if (ij == 0) sEa[m_] = sEPa[2*m_] + sEPa[2*m_+1];
    }
    __syncthreads();

    if (tid < 64) {
        int m_ = tid >> 5, lane = tid & 31;
        float v0 = sMa[m_*64 + lane], v1 = sMa[m_*64 + 32 + lane];
        float mx = fmaxf(v0, v1);
        #pragma unroll
        for (int off = 16; off >= 1; off >>= 1)
            mx = fmaxf(mx, __shfl_xor_sync(FULL, mx, off));
        int ib = __float_as_int(mx);
        float sc = __int_as_float((254 - (ib >> 23)) << 23);
        int sci = blockIdx.x*2 + m_;
        g_SM[(size_t)sci*64 + lane]      = v0 * sc;
        g_SM[(size_t)sci*64 + 32 + lane] = v1 * sc;
        if (lane == 0) g_ESM[sci] = sEa[m_] + (ib >> 23) - 127;
    }
}

// ---------------- pC: superchunk walk + chunk-boundary propagation + t-recursions ----------------
__global__ void __launch_bounds__(256) snlds_pC()
{
    __shared__ float sVW[16*8];     // per-superchunk entry/exit vectors (2 batches x 8 sc x 8)
    __shared__ int   sEVW[16];
    __shared__ float sBnd[256*8];
    __shared__ int   sEb[256];
    int tid = threadIdx.x;
    int dir = blockIdx.y;
    int bbase = blockIdx.x*2;

    // ---- phase 0: superchunk boundary walk (8 threads per batch, shuffle-parallel) ----
    if (tid < 16) {
        const unsigned M16 = 0xffffu;
        int bl = tid >> 3, k = tid & 7;
        int b = bbase + bl;
        int base = bl*8;               // lane base of this 8-group
        if (dir == 0) {
            // forward: v_{s+1} = v_s . SM[s]; thread k owns v[k], loads column k
            float v = g_epi[k] * g_ele[(size_t)b*Tt*8 + k];
            {
                float mx = v;
                mx = fmaxf(mx, __shfl_xor_sync(M16, mx, 1));
                mx = fmaxf(mx, __shfl_xor_sync(M16, mx, 2));
                mx = fmaxf(mx, __shfl_xor_sync(M16, mx, 4));
                int ib = __float_as_int(mx);
                v *= __int_as_float((254 - (ib >> 23)) << 23);
                int E = (ib >> 23) - 127;
                sVW[(base)*8 + k] = v;     // entry of sc 0
                if (k == 0) sEVW[base] = E;
                // serial walk with double-buffered column loads
                float col[8], coln[8];
                const float* SMb = g_SM + (size_t)(b*NS)*64;
                #pragma unroll
                for (int j = 0; j < 8; j++) col[j] = SMb[j*8 + k];
                for (int s = 0; s < NS-1; s++) {
                    if (s < NS-2) {
                        #pragma unroll
                        for (int j = 0; j < 8; j++) coln[j] = SMb[(s+1)*64 + j*8 + k];
                    }
                    float nv = 0.f;
                    #pragma unroll
                    for (int j = 0; j < 8; j++)
                        nv = fmaf(__shfl_sync(M16, v, base + j), col[j], nv);
                    float mx2 = nv;
                    mx2 = fmaxf(mx2, __shfl_xor_sync(M16, mx2, 1));
                    mx2 = fmaxf(mx2, __shfl_xor_sync(M16, mx2, 2));
                    mx2 = fmaxf(mx2, __shfl_xor_sync(M16, mx2, 4));
                    int ib2 = __float_as_int(mx2);
                    v = nv * __int_as_float((254 - (ib2 >> 23)) << 23);
                    E += (ib2 >> 23) - 127 + g_ESM[b*NS + s];
                    sVW[(base + s + 1)*8 + k] = v;
                    if (k == 0) sEVW[base + s + 1] = E;
                    #pragma unroll
                    for (int j = 0; j < 8; j++) col[j] = coln[j];
                }
            }
        } else {
            // backward: w_{s-1} = SM[s] . w_s; thread k owns w[k], loads row k
            float w = 1.0f;
            int F = 0;
            sVW[(base + NS-1)*8 + k] = w;
            if (k == 0) sEVW[base + NS-1] = 0;
            float row[8], rown[8];
            const float* SMb = g_SM + (size_t)(b*NS)*64;
            load8(row, SMb + (NS-1)*64 + k*8);
            for (int s = NS-1; s >= 1; s--) {
                if (s > 1) load8(rown, SMb + (s-1)*64 + k*8);
                float nw = 0.f;
                #pragma unroll
                for (int j = 0; j < 8; j++)
                    nw = fmaf(row[j], __shfl_sync(M16, w, base + j), nw);
                float mx2 = nw;
                mx2 = fmaxf(mx2, __shfl_xor_sync(M16, mx2, 1));
                mx2 = fmaxf(mx2, __shfl_xor_sync(M16, mx2, 2));
                mx2 = fmaxf(mx2, __shfl_xor_sync(M16, mx2, 4));
                int ib2 = __float_as_int(mx2);
                w = nw * __int_as_float((254 - (ib2 >> 23)) << 23);
                F += (ib2 >> 23) - 127 + g_ESM[b*NS + s];
                sVW[(base + s - 1)*8 + k] = w;
                if (k == 0) sEVW[base + s - 1] = F;
                #pragma unroll
                for (int j = 0; j < 8; j++) row[j] = rown[j];
            }
        }
    }
    __syncthreads();

    // ---- phase A: 16 walkers propagate chunk boundaries within superchunks ----
    if (tid < 16) {
        int bl = tid >> 3, s = tid & 7;
        int b = bbase + bl;
        int c0 = b*CC + s*SCn;
        if (dir == 0) {
            float v[8];
            load8(v, sVW + (size_t)(bl*8 + s)*8);
            int E = sEVW[bl*8 + s];
            for (int cc = 0; cc < SCn; cc++) {
                store8(sBnd + (size_t)(bl*128 + s*16 + cc)*8, v);
                sEb[bl*128 + s*16 + cc] = E;
                if (cc < SCn-1) {
                    float M[64];
                    #pragma unroll
                    for (int x = 0; x < 8; x++) load8(M + x*8, g_M + (size_t)(c0+cc)*64 + x*8);
                    float n[8];
                    #pragma unroll
                    for (int k = 0; k < 8; k++) {
                        float sv = v[0]*M[0*8+k];
                        #pragma unroll
                        for (int j = 1; j < 8; j++) sv = fmaf(v[j], M[j*8+k], sv);
                        n[k] = sv;
                    }
                    E += rescale8(n) + g_EM[c0+cc];
                    #pragma unroll
                    for (int k = 0; k < 8; k++) v[k] = n[k];
                }
            }
        } else {
            float w[8];
            load8(w, sVW + (size_t)(bl*8 + s)*8);
            int F = sEVW[bl*8 + s];
            for (int cc = SCn-1; cc >= 0; cc--) {
                store8(sBnd + (size_t)(bl*128 + s*16 + cc)*8, w);
                sEb[bl*128 + s*16 + cc] = F;
                if (cc > 0) {
                    float M[64];
                    #pragma unroll
                    for (int x = 0; x < 8; x++) load8(M + x*8, g_M + (size_t)(c0+cc)*64 + x*8);
                    float n[8];
                    #pragma unroll
                    for (int i = 0; i < 8; i++) {
                        float sv = M[i*8+0]*w[0];
                        #pragma unroll
                        for (int k = 1; k < 8; k++) sv = fmaf(M[i*8+k], w[k], sv);
                        n[i] = sv;
                    }
                    F += rescale8(n) + g_EM[c0+cc];
                    #pragma unroll
                    for (int k = 0; k < 8; k++) w[k] = n[k];
                }
            }
        }
    }
    __syncthreads();

    // ---- phase B: 256 chains = 2 batches x 128 chunks ----
    int bl = tid >> 7;
    int c  = tid & 127;
    int b  = bbase + bl;

    u64 q2[32];
    #pragma unroll
    for (int x = 0; x < 32; x++) q2[x] = *(const u64*)(g_eQ + 2*x);

    const float* eb = g_ele + (size_t)b*Tt*8;
    const float* bnd = sBnd + (size_t)(bl*128 + c)*8;

    if (dir == 0) {
        u64 a2[4];
        #pragma unroll
        for (int k2 = 0; k2 < 4; k2++) a2[k2] = *(const u64*)(bnd + 2*k2);
        int E = sEb[bl*128 + c];
        float* Ad = g_A + (size_t)b*Tt*8;
        int t0 = c*LC;
        if (c == 0) {
            float2 f0 = unpk(a2[0]), f1 = unpk(a2[1]), f2 = unpk(a2[2]), f3 = unpk(a2[3]);
            #pragma unroll
            for (int k2 = 0; k2 < 4; k2++) *(u64*)(Ad + 2*k2) = a2[k2];
            g_sig[b*Tt] = f0.x+f0.y+f1.x+f1.y+f2.x+f2.y+f3.x+f3.y;
            g_E[b*Tt] = E;
            t0 = 1;
        }
        int t1 = c*LC + LC;
        u64 el2[4];
        #pragma unroll
        for (int k2 = 0; k2 < 4; k2++) el2[k2] = *(const u64*)(eb + (size_t)t0*8 + 2*k2);
        for (int t = t0; t < t1; t++) {
            u64 eln[4];
            int tn = (t+1 < t1) ? (t+1) : t;
            #pragma unroll
            for (int k2 = 0; k2 < 4; k2++) eln[k2] = *(const u64*)(eb + (size_t)tn*8 + 2*k2);
            u64 ab[8];
            #pragma unroll
            for (int x = 0; x < 4; x++) {
                float2 f = unpk(a2[x]);
                ab[2*x] = packbb(f.x); ab[2*x+1] = packbb(f.y);
            }
            u64 n2[4];
            #pragma unroll
            for (int k2 = 0; k2 < 4; k2++) {
                u64 s = mul2(ab[0], q2[0*4 + k2]);
                #pragma unroll
                for (int j = 1; j < 8; j++) s = fma2(ab[j], q2[j*4 + k2], s);
                n2[k2] = mul2(s, el2[k2]);
            }
            float2 f0 = unpk(n2[0]), f1 = unpk(n2[1]), f2 = unpk(n2[2]), f3 = unpk(n2[3]);
            float mx = fmaxf(fmaxf(fmaxf(f0.x,f0.y),fmaxf(f1.x,f1.y)),
                             fmaxf(fmaxf(f2.x,f2.y),fmaxf(f3.x,f3.y)));
            int ib = __float_as_int(mx);
            E += (ib >> 23) - 127;
            float sc = __int_as_float((254 - (ib >> 23)) << 23);
            u64 scb = packbb(sc);
            #pragma unroll
            for (int k2 = 0; k2 < 4; k2++) {
                a2[k2] = mul2(n2[k2], scb);
                el2[k2] = eln[k2];
                *(u64*)(Ad + (size_t)t*8 + 2*k2) = a2[k2];
            }
            g_sig[b*Tt + t] = (f0.x+f0.y+f1.x+f1.y+f2.x+f2.y+f3.x+f3.y) * sc;
            g_E[b*Tt + t] = E;
        }
    } else {
        u64 w2[4];
        #pragma unroll
        for (int j2 = 0; j2 < 4; j2++) w2[j2] = *(const u64*)(bnd + 2*j2);
        int F = sEb[bl*128 + c];
        float* Bd = g_Bv + (size_t)b*Tt*8;
        int thi = c*LC + LC - 1;
        int lo  = c*LC;
        #pragma unroll
        for (int j2 = 0; j2 < 4; j2++) *(u64*)(Bd + (size_t)thi*8 + 2*j2) = w2[j2];
        g_F[b*Tt + thi] = F;
        u64 el2[4];
        #pragma unroll
        for (int j2 = 0; j2 < 4; j2++) el2[j2] = *(const u64*)(eb + (size_t)thi*8 + 2*j2);
        for (int t = thi - 1; t >= lo; t--) {
            u64 eln[4];
            int tn = (t > lo) ? t : lo;
            #pragma unroll
            for (int j2 = 0; j2 < 4; j2++) eln[j2] = *(const u64*)(eb + (size_t)tn*8 + 2*j2);
            u64 s2[4];
            #pragma unroll
            for (int j2 = 0; j2 < 4; j2++) s2[j2] = mul2(el2[j2], w2[j2]);
            float n[8];
            #pragma unroll
            for (int i = 0; i < 8; i++) {
                u64 acc = mul2(q2[i*4 + 0], s2[0]);
                acc = fma2(q2[i*4 + 1], s2[1], acc);
                acc = fma2(q2[i*4 + 2], s2[2], acc);
                acc = fma2(q2[i*4 + 3], s2[3], acc);
                float2 f = unpk(acc);
                n[i] = f.x + f.y;
            }
            F += rescale8(n);
            #pragma unroll
            for (int j2 = 0; j2 < 4; j2++) { w2[j2] = pack2(n[2*j2], n[2*j2+1]); el2[j2] = eln[j2]; }
            store8(Bd + (size_t)t*8, n);
            g_F[b*Tt + t] = F;
        }
    }
}

// ---------------- outputs: gamma, paired, log_Z ----------------
__global__ void __launch_bounds__(256) snlds_out(float* __restrict__ out)
{
    const unsigned FULL = 0xffffffffu;
    __shared__ float seQ[64];
    int tid = threadIdx.x;
    if (tid < 64) seQ[tid] = g_eQ[tid];
    __syncthreads();

    int gidx = blockIdx.x*32 + (tid >> 3);
    int i    = tid & 7;
    int t    = gidx & (Tt-1);
    int b    = gidx >> 11;

    float ai = g_A [(size_t)gidx*8 + i];
    float bi = g_Bv[(size_t)gidx*8 + i];
    float pr = ai * bi;
    float G = pr;
    G += __shfl_xor_sync(FULL, G, 1);
    G += __shfl_xor_sync(FULL, G, 2);
    G += __shfl_xor_sync(FULL, G, 4);
    float rG = 1.0f / G;
    out[(size_t)gidx*8 + i] = pr * rG;                  // gamma

    if (i == 0) {                                       // log_Z
        float lz;
        if (t == 0) lz = (lg2(g_sig[gidx]) + (float)g_E[gidx]) * LN2F + g_m[gidx];
        else        lz = (lg2(g_sig[gidx]) - lg2(g_sig[gidx-1])
                          + (float)(g_E[gidx] - g_E[gidx-1])) * LN2F + g_m[gidx];
        out[(size_t)GSZ + PSZ + gidx] = lz;
    }

    // paired
    int gn = (t < Tt-1) ? (gidx + 1) : gidx;
    float bj = g_Bv [(size_t)gn*8 + i];
    float ej = g_ele[(size_t)gn*8 + i];
    float cj = bj * ej;
    int dF = g_F[gidx] - g_F[gn];
    int sb = 127 - dF; if (sb < 1) sb = 1; if (sb > 254) sb = 254;
    float pnorm = rG * __int_as_float(sb << 23);

    int baseLane = tid & 24;
    float cb[8];
    #pragma unroll
    for (int j = 0; j < 8; j++) cb[j] = __shfl_sync(FULL, cj, baseLane + j);

    if (t < Tt-1) {
        float eA = ai * pnorm;
        size_t pbase = (size_t)GSZ + ((size_t)(b*(Tt-1) + t))*64 + (size_t)i*8;
        float4 p0, p1;
        p0.x = eA * seQ[i*8+0] * cb[0];
        p0.y = eA * seQ[i*8+1] * cb[1];
        p0.z = eA * seQ[i*8+2] * cb[2];
        p0.w = eA * seQ[i*8+3] * cb[3];
        p1.x = eA * seQ[i*8+4] * cb[4];
        p1.y = eA * seQ[i*8+5] * cb[5];
        p1.z = eA * seQ[i*8+6] * cb[6];
        p1.w = eA * seQ[i*8+7] * cb[7];
        *(float4*)(out + pbase)     = p0;
        *(float4*)(out + pbase + 4) = p1;
    }
}

extern "C" void kernel_launch(void* const* d_in, const int* in_sizes, int n_in,
                              void* d_out, int out_size) {
    const float* z         = (const float*)d_in[0];
    const float* pi        = (const float*)d_in[1];
    const float* Q         = (const float*)d_in[2];
    const float* init_mean = (const float*)d_in[3];
    const float* init_cov  = (const float*)d_in[4];
    const float* covs      = (const float*)d_in[5];
    const float* W1        = (const float*)d_in[6];
    const float* b1        = (const float*)d_in[7];
    const float* W2        = (const float*)d_in[8];
    const float* b2        = (const float*)d_in[9];
    float* out = (float*)d_out;

    cudaFuncSetAttribute(snlds_emis, cudaFuncAttributeMaxDynamicSharedMemorySize, EMIS_SMEM_BYTES);

    snlds_prep<<<1, 256>>>(pi, Q, init_cov, covs);
    snlds_emis<<<(Bb*Tt/2)/128, 128, EMIS_SMEM_BYTES>>>(z, W1, b1, W2, b2);
    snlds_pA<<<(Bb*CC*8)/256, 256>>>(z, init_mean);
    snlds_pC<<<dim3(Bb/2, 2), 256>>>();
    snlds_out<<<(Bb*Tt)/32, 256>>>(out);
}

// round 15
// speedup vs baseline: 1.0102x; 1.0030x over previous
#include <cuda_runtime.h>
#include <math.h>
#include <stdint.h>

#define Bb   64
#define Tt   2048
#define LDIM 16
#define HDIM 64
#define Kk   8
#define LC   16
#define CC   128             // Tt / LC
#define SCn  16              // chunks per superchunk
#define NS   8               // superchunks per batch = CC/SCn

#define LOG2E  1.4426950408889634f
#define LN2F   0.6931471805599453f
#define LOG2PI 1.8378770664093453f

#define GSZ  (Bb*Tt*Kk)            // gamma elements
#define PSZ  (Bb*(Tt-1)*Kk*Kk)     // paired elements

typedef unsigned long long u64;

// ---------------- f32x2 / MUFU helpers ----------------
__device__ __forceinline__ u64 fma2(u64 a, u64 b, u64 c){
    u64 d; asm("fma.rn.f32x2 %0, %1, %2, %3;" : "=l"(d) : "l"(a), "l"(b), "l"(c)); return d;
}
__device__ __forceinline__ u64 mul2(u64 a, u64 b){
    u64 d; asm("mul.rn.f32x2 %0, %1, %2;" : "=l"(d) : "l"(a), "l"(b)); return d;
}
__device__ __forceinline__ u64 packbb(float x){
    u64 d; asm("mov.b64 %0, {%1, %1};" : "=l"(d) : "f"(x)); return d;
}
__device__ __forceinline__ u64 pack2(float x, float y){
    u64 d; asm("mov.b64 %0, {%1, %2};" : "=l"(d) : "f"(x), "f"(y)); return d;
}
__device__ __forceinline__ float2 unpk(u64 u){
    float2 f; asm("mov.b64 {%0, %1}, %2;" : "=f"(f.x), "=f"(f.y) : "l"(u)); return f;
}
__device__ __forceinline__ float ex2(float x){ float r; asm("ex2.approx.ftz.f32 %0, %1;" : "=f"(r) : "f"(x)); return r; }
__device__ __forceinline__ float lg2(float x){ float r; asm("lg2.approx.f32 %0, %1;" : "=f"(r) : "f"(x)); return r; }

// ---------------- scratch ----------------
__device__ __align__(16) float g_ele[Bb*Tt*Kk];   // exp(le - m_t)
__device__ float g_m  [Bb*Tt];                    // m_t = max_k le
__device__ __align__(16) float g_A  [Bb*Tt*Kk];   // scaled forward
__device__ __align__(16) float g_Bv [Bb*Tt*Kk];   // scaled backward
__device__ float g_sig[Bb*Tt];                    // sum_k a-hat_t
__device__ int   g_E  [Bb*Tt];
__device__ int   g_F  [Bb*Tt];
__device__ __align__(16) float g_M  [Bb*CC*64];   // chunk matrices
__device__ int   g_EM [Bb*CC];
__device__ __align__(16) float g_SM [Bb*NS*64];   // superchunk matrices
__device__ int   g_ESM[Bb*NS];
__device__ __align__(16) float g_eQ [64];
__device__ float g_epi[8];
__device__ float g_Qlog[64];
__device__ float g_logpi[8];
__device__ float g_Linv0[Kk*LDIM*LDIM];
__device__ float g_LinvT[Kk*LDIM*LDIM];
__device__ float g_ld0[Kk];
__device__ float g_ldT[Kk];

__device__ __forceinline__ int rescale8(float* v) {
    float mx = v[0];
    #pragma unroll
    for (int k = 1; k < 8; k++) mx = fmaxf(mx, v[k]);
    int ib = __float_as_int(mx);
    int ee = (ib >> 23) - 127;
    float sc = __int_as_float((254 - (ib >> 23)) << 23);
    #pragma unroll
    for (int k = 0; k < 8; k++) v[k] *= sc;
    return ee;
}

__device__ __forceinline__ void load8(float* dst, const float* src) {
    float4 a = *(const float4*)src;
    float4 b = *(const float4*)(src + 4);
    dst[0]=a.x; dst[1]=a.y; dst[2]=a.z; dst[3]=a.w;
    dst[4]=b.x; dst[5]=b.y; dst[6]=b.z; dst[7]=b.w;
}
__device__ __forceinline__ void store8(float* dst, const float* v) {
    *(float4*)dst       = make_float4(v[0], v[1], v[2], v[3]);
    *(float4*)(dst + 4) = make_float4(v[4], v[5], v[6], v[7]);
}

// ---------------- prep ----------------
__global__ void snlds_prep(const float* __restrict__ pi,
                           const float* __restrict__ Q,
                           const float* __restrict__ init_cov,
                           const float* __restrict__ covs)
{
    __shared__ float S[16][256];
    int tid = threadIdx.x;         // 256 threads

    for (int e = tid; e < 4096; e += 256) {
        int m  = e >> 8;
        int ij = e & 255;
        int i  = ij >> 4, j = ij & 15;
        const float* C = (m < 8) ? (init_cov + m*256) : (covs + (m-8)*256);
        float s = (i == j) ? 1e-6f : 0.0f;
        #pragma unroll
        for (int d = 0; d < 16; d++) s = fmaf(C[i*16+d], C[j*16+d], s);
        S[m][ij] = s;
    }
    __syncthreads();

    int m = tid >> 4, r = tid & 15;
    for (int kk = 0; kk < 16; kk++) {
        if (r == kk) {
            float s = S[m][kk*16+kk];
            for (int e2 = 0; e2 < kk; e2++) { float v = S[m][kk*16+e2]; s -= v*v; }
            S[m][kk*16+kk] = sqrtf(s);
        }
        __syncthreads();
        if (r > kk) {
            float s = S[m][r*16+kk];
            for (int e2 = 0; e2 < kk; e2++) s -= S[m][r*16+e2]*S[m][kk*16+e2];
            S[m][r*16+kk] = s / S[m][kk*16+kk];
        }
        __syncthreads();
    }

    if (r == 0) {
        float s = 0.f;
        for (int d = 0; d < 16; d++) s += logf(S[m][d*16+d]);
        if (m < 8) g_ld0[m] = s; else g_ldT[m-8] = s;
    }

    {
        int c = r;
        float x[16];
        #pragma unroll
        for (int i2 = 0; i2 < 16; i2++) x[i2] = 0.f;
        for (int i2 = c; i2 < 16; i2++) {
            float s = (i2 == c) ? 1.0f : 0.0f;
            for (int e2 = c; e2 < i2; e2++) s -= S[m][i2*16+e2]*x[e2];
            x[i2] = s / S[m][i2*16+i2];
        }
        float* dst = (m < 8) ? (g_Linv0 + m*256) : (g_LinvT + (m-8)*256);
        for (int i2 = 0; i2 < 16; i2++) dst[i2*16 + c] = x[i2];
    }

    if (tid < 8) {
        float mx = -1e30f;
        for (int j = 0; j < 8; j++) mx = fmaxf(mx, Q[tid*8+j]);
        float se = 0.f;
        for (int j = 0; j < 8; j++) se += expf(Q[tid*8+j]-mx);
        float l = mx + logf(se);
        for (int j = 0; j < 8; j++) g_Qlog[tid*8+j] = Q[tid*8+j] - l;
    }
    if (tid == 8) {
        float mx = -1e30f;
        for (int j = 0; j < 8; j++) mx = fmaxf(mx, pi[j]);
        float se = 0.f;
        for (int j = 0; j < 8; j++) se += expf(pi[j]-mx);
        float l = mx + logf(se);
        for (int j = 0; j < 8; j++) g_logpi[j] = pi[j] - l;
    }
    __syncthreads();
    if (tid < 64) g_eQ[tid] = expf(g_Qlog[tid]);
    if (tid < 8)  g_epi[tid] = expf(g_logpi[tid]);
}

// ---------------- emissions: t>=1, 2 t per thread, 74.5KB smem ----------------
#define OFF_W1   0            // [k][d][j] * LOG2E  8192
#define OFF_W2   8192         // [k][j][d] * LN2F   8192
#define OFF_LVT  16384        // [k][e][d]          2048
#define OFF_B1   18432        // [k][j] * LOG2E     512
#define OFF_B2   18944        // [k][d]             128
#define OFF_LDT  19072        // 8
#define EMIS_SMEM_FLOATS 19080
#define EMIS_SMEM_BYTES  (EMIS_SMEM_FLOATS*4)

__device__ __forceinline__ float maha16(const u64* dd, const float* LT) {
    u64 dbb[16];
    #pragma unroll
    for (int x = 0; x < 8; x++) {
        float2 f = unpk(dd[x]);
        dbb[2*x]   = packbb(f.x);
        dbb[2*x+1] = packbb(f.y);
    }
    u64 y2[8];
    #pragma unroll
    for (int x = 0; x < 8; x++) y2[x] = 0ull;
    #pragma unroll
    for (int e = 0; e < 16; e++) {
        #pragma unroll
        for (int x = 0; x < 8; x++)
            y2[x] = fma2(*(const u64*)(LT + e*16 + 2*x), dbb[e], y2[x]);
    }
    u64 m2 = 0ull;
    #pragma unroll
    for (int x = 0; x < 8; x++) m2 = fma2(y2[x], y2[x], m2);
    float2 mm = unpk(m2);
    return mm.x + mm.y;
}

__global__ void __launch_bounds__(128) snlds_emis(const float* __restrict__ z,
                                                  const float* __restrict__ W1,
                                                  const float* __restrict__ b1,
                                                  const float* __restrict__ W2,
                                                  const float* __restrict__ b2)
{
    extern __shared__ float sm[];
    int tx = threadIdx.x;

    for (int i = tx; i < 8192; i += 128) {
        int k = i >> 10, rem = i & 1023;
        int j = rem >> 4, d = rem & 15;
        sm[OFF_W1 + k*1024 + d*64 + j] = LOG2E * W1[i];
        int d2 = rem >> 6, j2 = rem & 63;
        sm[OFF_W2 + k*1024 + j2*16 + d2] = LN2F * W2[i];
    }
    for (int i = tx; i < 2048; i += 128) {
        int k = i >> 8, rem = i & 255;
        int d = rem >> 4, e = rem & 15;
        sm[OFF_LVT + k*256 + e*16 + d] = g_LinvT[i];
    }
    for (int i = tx; i < 512; i += 128) sm[OFF_B1 + i] = LOG2E * b1[i];
    if (tx < 128) sm[OFF_B2 + tx] = b2[tx];
    if (tx < 8) sm[OFF_LDT + tx] = g_ldT[tx];
    __syncthreads();

    int p = blockIdx.x*128 + tx;         // 65536 t-pairs
    int b = p >> 10;
    int t0 = (p & 1023) << 1;
    const float* zb = z + ((size_t)b*Tt + t0)*LDIM;

    u64 v0bb[16], v1bb[16];
    {
        float tmp[16];
        const float* z0 = (p == 0) ? zb : (zb - LDIM);   // OOB clamp only
        load8(tmp, z0); load8(tmp+8, z0+8);
        #pragma unroll
        for (int d = 0; d < 16; d++) v0bb[d] = packbb(tmp[d]);
        load8(tmp, zb); load8(tmp+8, zb+8);
        #pragma unroll
        for (int d = 0; d < 16; d++) v1bb[d] = packbb(tmp[d]);
    }

    float le0[8], le1[8];

    #pragma unroll 1
    for (int k = 0; k < 8; k++) {
        const float* w1k = sm + OFF_W1 + k*1024;
        const float* w2k = sm + OFF_W2 + k*1024;
        u64 mu0[8], mu1[8];
        #pragma unroll
        for (int x = 0; x < 8; x++) {
            u64 bp = *(const u64*)(sm + OFF_B2 + k*16 + 2*x);
            mu0[x] = bp; mu1[x] = bp;
        }
        #pragma unroll 1
        for (int jg = 0; jg < 16; jg++) {
            const float* w1j = w1k + jg*4;
            u64 bA = *(const u64*)(sm + OFF_B1 + k*64 + jg*4);
            u64 bB = *(const u64*)(sm + OFF_B1 + k*64 + jg*4 + 2);
            u64 aA0 = bA, aA1 = bA, aB0 = bB, aB1 = bB;
            #pragma unroll
            for (int d = 0; d < 16; d++) {
                u64 wA = *(const u64*)(w1j + d*64);
                u64 wB = *(const u64*)(w1j + d*64 + 2);
                aA0 = fma2(wA, v0bb[d], aA0);
                aA1 = fma2(wA, v1bb[d], aA1);
                aB0 = fma2(wB, v0bb[d], aB0);
                aB1 = fma2(wB, v1bb[d], aB1);
            }
            float2 fA0 = unpk(aA0), fB0 = unpk(aB0), fA1 = unpk(aA1), fB1 = unpk(aB1);
            u64 h00 = packbb(lg2(1.0f + ex2(fA0.x)));
            u64 h01 = packbb(lg2(1.0f + ex2(fA0.y)));
            u64 h02 = packbb(lg2(1.0f + ex2(fB0.x)));
            u64 h03 = packbb(lg2(1.0f + ex2(fB0.y)));
            u64 h10 = packbb(lg2(1.0f + ex2(fA1.x)));
            u64 h11 = packbb(lg2(1.0f + ex2(fA1.y)));
            u64 h12 = packbb(lg2(1.0f + ex2(fB1.x)));
            u64 h13 = packbb(lg2(1.0f + ex2(fB1.y)));
            const float* w2j = w2k + jg*64;
            #pragma unroll
            for (int x = 0; x < 8; x++) {
                u64 w0 = *(const u64*)(w2j +  0 + 2*x);
                u64 w1_= *(const u64*)(w2j + 16 + 2*x);
                u64 w2_= *(const u64*)(w2j + 32 + 2*x);
                u64 w3_= *(const u64*)(w2j + 48 + 2*x);
                mu0[x] = fma2(w0, h00, mu0[x]);
                mu0[x] = fma2(w1_, h01, mu0[x]);
                mu0[x] = fma2(w2_, h02, mu0[x]);
                mu0[x] = fma2(w3_, h03, mu0[x]);
                mu1[x] = fma2(w0, h10, mu1[x]);
                mu1[x] = fma2(w1_, h11, mu1[x]);
                mu1[x] = fma2(w2_, h12, mu1[x]);
                mu1[x] = fma2(w3_, h13, mu1[x]);
            }
        }
        u64 neg1 = pack2(-1.0f, -1.0f);
        u64 dd[8];
        float tmp[16];
        load8(tmp, zb); load8(tmp+8, zb+8);
        #pragma unroll
        for (int x = 0; x < 8; x++)
            dd[x] = fma2(mu0[x], neg1, pack2(tmp[2*x], tmp[2*x+1]));
        float maha0 = maha16(dd, sm + OFF_LVT + k*256);
        le0[k] = -0.5f*maha0 - sm[OFF_LDT + k] - 8.0f*LOG2PI;

        load8(tmp, zb+16); load8(tmp+8, zb+24);
        #pragma unroll
        for (int x = 0; x < 8; x++)
            dd[x] = fma2(mu1[x], neg1, pack2(tmp[2*x], tmp[2*x+1]));
        float maha1 = maha16(dd, sm + OFF_LVT + k*256);
        le1[k] = -0.5f*maha1 - sm[OFF_LDT + k] - 8.0f*LOG2PI;
    }

    size_t g0 = (size_t)b*Tt + t0;
    if (t0 != 0) {                       // t=0 handled in snlds_pA
        float m = le0[0];
        #pragma unroll
        for (int k = 1; k < 8; k++) m = fmaxf(m, le0[k]);
        g_m[g0] = m;
        float v[8];
        #pragma unroll
        for (int k = 0; k < 8; k++) v[k] = ex2((le0[k] - m) * LOG2E);
        store8(g_ele + g0*8, v);
    }
    {
        float m = le1[0];
        #pragma unroll
        for (int k = 1; k < 8; k++) m = fmaxf(m, le1[k]);
        g_m[g0+1] = m;
        float v[8];
        #pragma unroll
        for (int k = 0; k < 8; k++) v[k] = ex2((le1[k] - m) * LOG2E);
        store8(g_ele + (g0+1)*8, v);
    }
}

// ---------------- pA: chunk products + in-block superchunk tree (+ t=0 emissions) ----------------
__global__ void __launch_bounds__(256) snlds_pA(const float* __restrict__ z,
                                                const float* __restrict__ init_mean)
{
    __shared__ float sMa[32*64];
    __shared__ float sPa[16*64];
    __shared__ int   sEa[32];
    __shared__ int   sEPa[16];

    int tid = threadIdx.x;
    int gt = blockIdx.x*256 + tid;
    int i = gt & 7;
    int chain = gt >> 3;
    int c = chain & (CC-1);
    int b = chain >> 7;
    int lc = tid >> 3;

    if (blockIdx.x == 0 && tid < 64) {
        int bb = tid;
        const float* zr = z + (size_t)bb*Tt*LDIM;
        float zc[16];
        load8(zc, zr); load8(zc+8, zr+8);
        float le[8];
        #pragma unroll 1
        for (int k = 0; k < 8; k++) {
            float diff[16];
            #pragma unroll
            for (int d = 0; d < 16; d++) diff[d] = zc[d] - init_mean[k*16+d];
            float maha = 0.f;
            #pragma unroll
            for (int d = 0; d < 16; d++) {
                float y = 0.f;
                #pragma unroll
                for (int e = 0; e < 16; e++) y = fmaf(g_Linv0[k*256 + d*16 + e], diff[e], y);
                maha = fmaf(y, y, maha);
            }
            le[k] = -0.5f*maha - g_ld0[k] - 8.0f*LOG2PI;
        }
        float m = le[0];
        #pragma unroll
        for (int k = 1; k < 8; k++) m = fmaxf(m, le[k]);
        g_m[(size_t)bb*Tt] = m;
        float v[8];
        #pragma unroll
        for (int k = 0; k < 8; k++) v[k] = ex2((le[k] - m) * LOG2E);
        store8(g_ele + (size_t)bb*Tt*8, v);
    }

    u64 q2[32];
    #pragma unroll
    for (int x = 0; x < 32; x++) q2[x] = *(const u64*)(g_eQ + 2*x);

    u64 r2[4];
    #pragma unroll
    for (int k2 = 0; k2 < 4; k2++)
        r2[k2] = pack2((i == 2*k2) ? 1.0f : 0.0f, (i == 2*k2+1) ? 1.0f : 0.0f);
    int E = 0;

    const float* eb = g_ele + ((size_t)b*Tt)*8;
    int t0 = c*LC + ((c == 0) ? 1 : 0);
    int t1 = c*LC + LC;

    u64 el2[4];
    #pragma unroll
    for (int k2 = 0; k2 < 4; k2++) el2[k2] = *(const u64*)(eb + (size_t)t0*8 + 2*k2);

    for (int t = t0; t < t1; t++) {
        u64 eln[4];
        int tn = (t+1 < t1) ? (t+1) : t;
        #pragma unroll
        for (int k2 = 0; k2 < 4; k2++) eln[k2] = *(const u64*)(eb + (size_t)tn*8 + 2*k2);

        u64 rb[8];
        #pragma unroll
        for (int x = 0; x < 4; x++) {
            float2 f = unpk(r2[x]);
            rb[2*x] = packbb(f.x); rb[2*x+1] = packbb(f.y);
        }
        u64 n2[4];
        #pragma unroll
        for (int k2 = 0; k2 < 4; k2++) {
            u64 s = mul2(rb[0], q2[0*4 + k2]);
            #pragma unroll
            for (int j = 1; j < 8; j++) s = fma2(rb[j], q2[j*4 + k2], s);
            n2[k2] = mul2(s, el2[k2]);
        }
        float2 f0 = unpk(n2[0]), f1 = unpk(n2[1]), f2 = unpk(n2[2]), f3 = unpk(n2[3]);
        float mx = fmaxf(fmaxf(fmaxf(f0.x,f0.y),fmaxf(f1.x,f1.y)),
                         fmaxf(fmaxf(f2.x,f2.y),fmaxf(f3.x,f3.y)));
        int ib = __float_as_int(mx);
        E += (ib >> 23) - 127;
        u64 scb = packbb(__int_as_float((254 - (ib >> 23)) << 23));
        #pragma unroll
        for (int k2 = 0; k2 < 4; k2++) { r2[k2] = mul2(n2[k2], scb); el2[k2] = eln[k2]; }
    }

    const unsigned FULL = 0xffffffffu;
    int Emax = E;
    Emax = max(Emax, __shfl_xor_sync(FULL, Emax, 1));
    Emax = max(Emax, __shfl_xor_sync(FULL, Emax, 2));
    Emax = max(Emax, __shfl_xor_sync(FULL, Emax, 4));
    int d = E - Emax; if (d < -126) d = -126;
    u64 scb = packbb(__int_as_float((127 + d) << 23));
    #pragma unroll
    for (int k2 = 0; k2 < 4; k2++) {
        u64 val = mul2(r2[k2], scb);
        *(u64*)(g_M + (size_t)chain*64 + i*8 + 2*k2) = val;
        *(u64*)(sMa + lc*64 + i*8 + 2*k2) = val;
    }
    if (i == 0) { g_EM[chain] = Emax; sEa[lc] = Emax; }
    __syncthreads();

    // tree reduce 32 -> 2 superchunks
    for (int e = tid; e < 16*64; e += 256) {
        int m_ = e >> 6, ij = e & 63, ii = ij >> 3, jj = ij & 7;
        const float* L = sMa + (2*m_)*64;
        const float* R = sMa + (2*m_+1)*64;
        float s = 0.f;
        #pragma unroll
        for (int k = 0; k < 8; k++) s = fmaf(L[ii*8+k], R[k*8+jj], s);
        sPa[e] = s;
        if (ij == 0) sEPa[m_] = sEa[2*m_] + sEa[2*m_+1];
    }
    __syncthreads();
    for (int e = tid; e < 8*64; e += 256) {
        int m_ = e >> 6, ij = e & 63, ii = ij >> 3, jj = ij & 7;
        const float* L = sPa + (2*m_)*64;
        const float* R = sPa + (2*m_+1)*64;
        float s = 0.f;
        #pragma unroll
        for (int k = 0; k < 8; k++) s = fmaf(L[ii*8+k], R[k*8+jj], s);
        sMa[e] = s;
        if (ij == 0) sEa[m_] = sEPa[2*m_] + sEPa[2*m_+1];
    }
    __syncthreads();
    for (int e = tid; e < 4*64; e += 256) {
        int m_ = e >> 6, ij = e & 63, ii = ij >> 3, jj = ij & 7;
        const float* L = sMa + (2*m_)*64;
        const float* R = sMa + (2*m_+1)*64;
        float s = 0.f;
        #pragma unroll
        for (int k = 0; k < 8; k++) s = fmaf(L[ii*8+k], R[k*8+jj], s);
        sPa[e] = s;
        if (ij == 0) sEPa[m_] = sEa[2*m_] + sEa[2*m_+1];
    }
    __syncthreads();
    for (int e = tid; e < 2*64; e += 256) {
        int m_ = e >> 6, ij = e & 63, ii = ij >> 3, jj = ij & 7;
        const float* L = sPa + (2*m_)*64;
        const float* R = sPa + (2*m_+1)*64;
        float s = 0.f;
        #pragma unroll
        for (int k = 0; k < 8; k++) s = fmaf(L[ii*8+k], R[k*8+jj], s);
        sMa[e] = s;
        if (ij == 0) sEa[m_] = sEPa[2*m_] + sEPa[2*m_+1];
    }
    __syncthreads();

    if (tid < 64) {
        int m_ = tid >> 5, lane = tid & 31;
        float v0 = sMa[m_*64 + lane], v1 = sMa[m_*64 + 32 + lane];
        float mx = fmaxf(v0, v1);
        #pragma unroll
        for (int off = 16; off >= 1; off >>= 1)
            mx = fmaxf(mx, __shfl_xor_sync(FULL, mx, off));
        int ib = __float_as_int(mx);
        float sc = __int_as_float((254 - (ib >> 23)) << 23);
        int sci = blockIdx.x*2 + m_;
        g_SM[(size_t)sci*64 + lane]      = v0 * sc;
        g_SM[(size_t)sci*64 + 32 + lane] = v1 * sc;
        if (lane == 0) g_ESM[sci] = sEa[m_] + (ib >> 23) - 127;
    }
}

// ---------------- pC: superchunk walk + chunk-boundary propagation + t-recursions ----------------
__global__ void __launch_bounds__(256) snlds_pC()
{
    __shared__ float sVW[16*8];     // per-superchunk entry/exit vectors (2 batches x 8 sc x 8)
    __shared__ int   sEVW[16];
    __shared__ float sBnd[256*8];
    __shared__ int   sEb[256];
    int tid = threadIdx.x;
    int dir = blockIdx.y;
    int bbase = blockIdx.x*2;

    // ---- phase 0: superchunk boundary walk (8 threads per batch, shuffle-parallel) ----
    if (tid < 16) {
        const unsigned M16 = 0xffffu;
        int bl = tid >> 3, k = tid & 7;
        int b = bbase + bl;
        int base = bl*8;               // lane base of this 8-group
        if (dir == 0) {
            // forward: v_{s+1} = v_s . SM[s]; thread k owns v[k], loads column k
            float v = g_epi[k] * g_ele[(size_t)b*Tt*8 + k];
            {
                float mx = v;
                mx = fmaxf(mx, __shfl_xor_sync(M16, mx, 1));
                mx = fmaxf(mx, __shfl_xor_sync(M16, mx, 2));
                mx = fmaxf(mx, __shfl_xor_sync(M16, mx, 4));
                int ib = __float_as_int(mx);
                v *= __int_as_float((254 - (ib >> 23)) << 23);
                int E = (ib >> 23) - 127;
                sVW[(base)*8 + k] = v;     // entry of sc 0
                if (k == 0) sEVW[base] = E;
                // serial walk with double-buffered column loads
                float col[8], coln[8];
                const float* SMb = g_SM + (size_t)(b*NS)*64;
                #pragma unroll
                for (int j = 0; j < 8; j++) col[j] = SMb[j*8 + k];
                for (int s = 0; s < NS-1; s++) {
                    if (s < NS-2) {
                        #pragma unroll
                        for (int j = 0; j < 8; j++) coln[j] = SMb[(s+1)*64 + j*8 + k];
                    }
                    float nv = 0.f;
                    #pragma unroll
                    for (int j = 0; j < 8; j++)
                        nv = fmaf(__shfl_sync(M16, v, base + j), col[j], nv);
                    float mx2 = nv;
                    mx2 = fmaxf(mx2, __shfl_xor_sync(M16, mx2, 1));
                    mx2 = fmaxf(mx2, __shfl_xor_sync(M16, mx2, 2));
                    mx2 = fmaxf(mx2, __shfl_xor_sync(M16, mx2, 4));
                    int ib2 = __float_as_int(mx2);
                    v = nv * __int_as_float((254 - (ib2 >> 23)) << 23);
                    E += (ib2 >> 23) - 127 + g_ESM[b*NS + s];
                    sVW[(base + s + 1)*8 + k] = v;
                    if (k == 0) sEVW[base + s + 1] = E;
                    #pragma unroll
                    for (int j = 0; j < 8; j++) col[j] = coln[j];
                }
            }
        } else {
            // backward: w_{s-1} = SM[s] . w_s; thread k owns w[k], loads row k
            float w = 1.0f;
            int F = 0;
            sVW[(base + NS-1)*8 + k] = w;
            if (k == 0) sEVW[base + NS-1] = 0;
            float row[8], rown[8];
            const float* SMb = g_SM + (size_t)(b*NS)*64;
            load8(row, SMb + (NS-1)*64 + k*8);
            for (int s = NS-1; s >= 1; s--) {
                if (s > 1) load8(rown, SMb + (s-1)*64 + k*8);
                float nw = 0.f;
                #pragma unroll
                for (int j = 0; j < 8; j++)
                    nw = fmaf(row[j], __shfl_sync(M16, w, base + j), nw);
                float mx2 = nw;
                mx2 = fmaxf(mx2, __shfl_xor_sync(M16, mx2, 1));
                mx2 = fmaxf(mx2, __shfl_xor_sync(M16, mx2, 2));
                mx2 = fmaxf(mx2, __shfl_xor_sync(M16, mx2, 4));
                int ib2 = __float_as_int(mx2);
                w = nw * __int_as_float((254 - (ib2 >> 23)) << 23);
                F += (ib2 >> 23) - 127 + g_ESM[b*NS + s];
                sVW[(base + s - 1)*8 + k] = w;
                if (k == 0) sEVW[base + s - 1] = F;
                #pragma unroll
                for (int j = 0; j < 8; j++) row[j] = rown[j];
            }
        }
    }
    __syncthreads();

    // ---- phase A: 16 walkers propagate chunk boundaries within superchunks ----
    if (tid < 16) {
        int bl = tid >> 3, s = tid & 7;
        int b = bbase + bl;
        int c0 = b*CC + s*SCn;
        if (dir == 0) {
            float v[8];
            load8(v, sVW + (size_t)(bl*8 + s)*8);
            int E = sEVW[bl*8 + s];
            for (int cc = 0; cc < SCn; cc++) {
                store8(sBnd + (size_t)(bl*128 + s*16 + cc)*8, v);
                sEb[bl*128 + s*16 + cc] = E;
                if (cc < SCn-1) {
                    float M[64];
                    #pragma unroll
                    for (int x = 0; x < 8; x++) load8(M + x*8, g_M + (size_t)(c0+cc)*64 + x*8);
                    float n[8];
                    #pragma unroll
                    for (int k = 0; k < 8; k++) {
                        float sv = v[0]*M[0*8+k];
                        #pragma unroll
                        for (int j = 1; j < 8; j++) sv = fmaf(v[j], M[j*8+k], sv);
                        n[k] = sv;
                    }
                    E += rescale8(n) + g_EM[c0+cc];
                    #pragma unroll
                    for (int k = 0; k < 8; k++) v[k] = n[k];
                }
            }
        } else {
            float w[8];
            load8(w, sVW + (size_t)(bl*8 + s)*8);
            int F = sEVW[bl*8 + s];
            for (int cc = SCn-1; cc >= 0; cc--) {
                store8(sBnd + (size_t)(bl*128 + s*16 + cc)*8, w);
                sEb[bl*128 + s*16 + cc] = F;
                if (cc > 0) {
                    float M[64];
                    #pragma unroll
                    for (int x = 0; x < 8; x++) load8(M + x*8, g_M + (size_t)(c0+cc)*64 + x*8);
                    float n[8];
                    #pragma unroll
                    for (int i = 0; i < 8; i++) {
                        float sv = M[i*8+0]*w[0];
                        #pragma unroll
                        for (int k = 1; k < 8; k++) sv = fmaf(M[i*8+k], w[k], sv);
                        n[i] = sv;
                    }
                    F += rescale8(n) + g_EM[c0+cc];
                    #pragma unroll
                    for (int k = 0; k < 8; k++) w[k] = n[k];
                }
            }
        }
    }
    __syncthreads();

    // ---- phase B: 256 chains = 2 batches x 128 chunks ----
    int bl = tid >> 7;
    int c  = tid & 127;
    int b  = bbase + bl;

    u64 q2[32];
    #pragma unroll
    for (int x = 0; x < 32; x++) q2[x] = *(const u64*)(g_eQ + 2*x);

    const float* eb = g_ele + (size_t)b*Tt*8;
    const float* bnd = sBnd + (size_t)(bl*128 + c)*8;

    if (dir == 0) {
        u64 a2[4];
        #pragma unroll
        for (int k2 = 0; k2 < 4; k2++) a2[k2] = *(const u64*)(bnd + 2*k2);
        int E = sEb[bl*128 + c];
        float* Ad = g_A + (size_t)b*Tt*8;
        int t0 = c*LC;
        if (c == 0) {
            float2 f0 = unpk(a2[0]), f1 = unpk(a2[1]), f2 = unpk(a2[2]), f3 = unpk(a2[3]);
            #pragma unroll
            for (int k2 = 0; k2 < 4; k2++) *(u64*)(Ad + 2*k2) = a2[k2];
            g_sig[b*Tt] = f0.x+f0.y+f1.x+f1.y+f2.x+f2.y+f3.x+f3.y;
            g_E[b*Tt] = E;
            t0 = 1;
        }
        int t1 = c*LC + LC;
        u64 el2[4];
        #pragma unroll
        for (int k2 = 0; k2 < 4; k2++) el2[k2] = *(const u64*)(eb + (size_t)t0*8 + 2*k2);
        for (int t = t0; t < t1; t++) {
            u64 eln[4];
            int tn = (t+1 < t1) ? (t+1) : t;
            #pragma unroll
            for (int k2 = 0; k2 < 4; k2++) eln[k2] = *(const u64*)(eb + (size_t)tn*8 + 2*k2);
            u64 ab[8];
            #pragma unroll
            for (int x = 0; x < 4; x++) {
                float2 f = unpk(a2[x]);
                ab[2*x] = packbb(f.x); ab[2*x+1] = packbb(f.y);
            }
            u64 n2[4];
            #pragma unroll
            for (int k2 = 0; k2 < 4; k2++) {
                u64 s = mul2(ab[0], q2[0*4 + k2]);
                #pragma unroll
                for (int j = 1; j < 8; j++) s = fma2(ab[j], q2[j*4 + k2], s);
                n2[k2] = mul2(s, el2[k2]);
            }
            float2 f0 = unpk(n2[0]), f1 = unpk(n2[1]), f2 = unpk(n2[2]), f3 = unpk(n2[3]);
            float mx = fmaxf(fmaxf(fmaxf(f0.x,f0.y),fmaxf(f1.x,f1.y)),
                             fmaxf(fmaxf(f2.x,f2.y),fmaxf(f3.x,f3.y)));
            int ib = __float_as_int(mx);
            E += (ib >> 23) - 127;
            float sc = __int_as_float((254 - (ib >> 23)) << 23);
            u64 scb = packbb(sc);
            #pragma unroll
            for (int k2 = 0; k2 < 4; k2++) {
                a2[k2] = mul2(n2[k2], scb);
                el2[k2] = eln[k2];
                *(u64*)(Ad + (size_t)t*8 + 2*k2) = a2[k2];
            }
            g_sig[b*Tt + t] = (f0.x+f0.y+f1.x+f1.y+f2.x+f2.y+f3.x+f3.y) * sc;
            g_E[b*Tt + t] = E;
        }
    } else {
        u64 w2[4];
        #pragma unroll
        for (int j2 = 0; j2 < 4; j2++) w2[j2] = *(const u64*)(bnd + 2*j2);
        int F = sEb[bl*128 + c];
        float* Bd = g_Bv + (size_t)b*Tt*8;
        int thi = c*LC + LC - 1;
        int lo  = c*LC;
        #pragma unroll
        for (int j2 = 0; j2 < 4; j2++) *(u64*)(Bd + (size_t)thi*8 + 2*j2) = w2[j2];
        g_F[b*Tt + thi] = F;
        u64 el2[4];
        #pragma unroll
        for (int j2 = 0; j2 < 4; j2++) el2[j2] = *(const u64*)(eb + (size_t)thi*8 + 2*j2);
        for (int t = thi - 1; t >= lo; t--) {
            u64 eln[4];
            int tn = (t > lo) ? t : lo;
            #pragma unroll
            for (int j2 = 0; j2 < 4; j2++) eln[j2] = *(const u64*)(eb + (size_t)tn*8 + 2*j2);
            u64 s2[4];
            #pragma unroll
            for (int j2 = 0; j2 < 4; j2++) s2[j2] = mul2(el2[j2], w2[j2]);
            float n[8];
            #pragma unroll
            for (int i = 0; i < 8; i++) {
                u64 acc = mul2(q2[i*4 + 0], s2[0]);
                acc = fma2(q2[i*4 + 1], s2[1], acc);
                acc = fma2(q2[i*4 + 2], s2[2], acc);
                acc = fma2(q2[i*4 + 3], s2[3], acc);
                float2 f = unpk(acc);
                n[i] = f.x + f.y;
            }
            F += rescale8(n);
            #pragma unroll
            for (int j2 = 0; j2 < 4; j2++) { w2[j2] = pack2(n[2*j2], n[2*j2+1]); el2[j2] = eln[j2]; }
            store8(Bd + (size_t)t*8, n);
            g_F[b*Tt + t] = F;
        }
    }
}

// ---------------- outputs: gamma, paired, log_Z ----------------
__global__ void __launch_bounds__(256) snlds_out(float* __restrict__ out)
{
    const unsigned FULL = 0xffffffffu;
    __shared__ float seQ[64];
    int tid = threadIdx.x;
    if (tid < 64) seQ[tid] = g_eQ[tid];
    __syncthreads();

    int gidx = blockIdx.x*32 + (tid >> 3);
    int i    = tid & 7;
    int t    = gidx & (Tt-1);
    int b    = gidx >> 11;

    float ai = g_A [(size_t)gidx*8 + i];
    float bi = g_Bv[(size_t)gidx*8 + i];
    float pr = ai * bi;
    float G = pr;
    G += __shfl_xor_sync(FULL, G, 1);
    G += __shfl_xor_sync(FULL, G, 2);
    G += __shfl_xor_sync(FULL, G, 4);
    float rG = 1.0f / G;
    out[(size_t)gidx*8 + i] = pr * rG;                  // gamma

    if (i == 0) {                                       // log_Z
        float lz;
        if (t == 0) lz = (lg2(g_sig[gidx]) + (float)g_E[gidx]) * LN2F + g_m[gidx];
        else        lz = (lg2(g_sig[gidx]) - lg2(g_sig[gidx-1])
                          + (float)(g_E[gidx] - g_E[gidx-1])) * LN2F + g_m[gidx];
        out[(size_t)GSZ + PSZ + gidx] = lz;
    }

    // paired
    int gn = (t < Tt-1) ? (gidx + 1) : gidx;
    float bj = g_Bv [(size_t)gn*8 + i];
    float ej = g_ele[(size_t)gn*8 + i];
    float cj = bj * ej;
    int dF = g_F[gidx] - g_F[gn];
    int sb = 127 - dF; if (sb < 1) sb = 1; if (sb > 254) sb = 254;
    float pnorm = rG * __int_as_float(sb << 23);

    int baseLane = tid & 24;
    float cb[8];
    #pragma unroll
    for (int j = 0; j < 8; j++) cb[j] = __shfl_sync(FULL, cj, baseLane + j);

    if (t < Tt-1) {
        float eA = ai * pnorm;
        size_t pbase = (size_t)GSZ + ((size_t)(b*(Tt-1) + t))*64 + (size_t)i*8;
        float4 p0, p1;
        p0.x = eA * seQ[i*8+0] * cb[0];
        p0.y = eA * seQ[i*8+1] * cb[1];
        p0.z = eA * seQ[i*8+2] * cb[2];
        p0.w = eA * seQ[i*8+3] * cb[3];
        p1.x = eA * seQ[i*8+4] * cb[4];
        p1.y = eA * seQ[i*8+5] * cb[5];
        p1.z = eA * seQ[i*8+6] * cb[6];
        p1.w = eA * seQ[i*8+7] * cb[7];
        *(float4*)(out + pbase)     = p0;
        *(float4*)(out + pbase + 4) = p1;
    }
}

extern "C" void kernel_launch(void* const* d_in, const int* in_sizes, int n_in,
                              void* d_out, int out_size) {
    const float* z         = (const float*)d_in[0];
    const float* pi        = (const float*)d_in[1];
    const float* Q         = (const float*)d_in[2];
    const float* init_mean = (const float*)d_in[3];
    const float* init_cov  = (const float*)d_in[4];
    const float* covs      = (const float*)d_in[5];
    const float* W1        = (const float*)d_in[6];
    const float* b1        = (const float*)d_in[7];
    const float* W2        = (const float*)d_in[8];
    const float* b2        = (const float*)d_in[9];
    float* out = (float*)d_out;

    cudaFuncSetAttribute(snlds_emis, cudaFuncAttributeMaxDynamicSharedMemorySize, EMIS_SMEM_BYTES);

    snlds_prep<<<1, 256>>>(pi, Q, init_cov, covs);
    snlds_emis<<<(Bb*Tt/2)/128, 128, EMIS_SMEM_BYTES>>>(z, W1, b1, W2, b2);
    snlds_pA<<<(Bb*CC*8)/256, 256>>>(z, init_mean);
    snlds_pC<<<dim3(Bb/2, 2), 256>>>();
    snlds_out<<<(Bb*Tt)/32, 256>>>(out);
}